// round 10
// baseline (speedup 1.0000x reference)
#include <cuda_runtime.h>
#include <cuda_fp16.h>
#include <math.h>
#include <stddef.h>
#include <stdint.h>

#define BSZ   4
#define TLEN  2048
#define DIM_  1024
#define NH    16
#define HDIM  64
#define BT    (BSZ * TLEN)        // 8192

// Scratch (device-global; no runtime allocation)
__device__ __half g_Xh [(size_t)BT * DIM_];               // x in half
__device__ __half g_Wqh[(size_t)DIM_ * DIM_];
__device__ __half g_Wkh[(size_t)DIM_ * DIM_];
__device__ __half g_Wvh[(size_t)DIM_ * DIM_];
__device__ __half g_Woh[(size_t)DIM_ * DIM_];
__device__ __half g_Qh[(size_t)BSZ * NH * TLEN * HDIM];   // [bh][t][d], rope+scale
__device__ __half g_Kh[(size_t)BSZ * NH * TLEN * HDIM];   // [bh][t][d], rope
__device__ __half g_Vh[(size_t)BSZ * NH * HDIM * TLEN];   // [bh][d][t]
__device__ __half g_Oh[(size_t)BT * DIM_];                // [bt][dim] attention out
__device__ float  g_Hh[(size_t)BT * DIM_];                // residual sum

// ---------------------------------------------------------------------------
// helpers
// ---------------------------------------------------------------------------
__device__ __forceinline__ void mma_f16(float c[4],
                                        const uint32_t a[4],
                                        uint32_t b0, uint32_t b1) {
    asm volatile(
        "mma.sync.aligned.m16n8k16.row.col.f32.f16.f16.f32 "
        "{%0,%1,%2,%3},{%4,%5,%6,%7},{%8,%9},{%0,%1,%2,%3};"
        : "+f"(c[0]), "+f"(c[1]), "+f"(c[2]), "+f"(c[3])
        : "r"(a[0]), "r"(a[1]), "r"(a[2]), "r"(a[3]),
          "r"(b0), "r"(b1));
}

__device__ __forceinline__ void ldsm4(uint32_t& r0, uint32_t& r1,
                                      uint32_t& r2, uint32_t& r3,
                                      uint32_t addr) {
    asm volatile("ldmatrix.sync.aligned.m8n8.x4.shared.b16 {%0,%1,%2,%3}, [%4];"
                 : "=r"(r0), "=r"(r1), "=r"(r2), "=r"(r3) : "r"(addr));
}

__device__ __forceinline__ uint32_t pack_h2(float lo, float hi) {
    __half2 h = __floats2half2_rn(lo, hi);
    return *(uint32_t*)&h;
}

__device__ __forceinline__ void cp16(uint32_t dst_smem, const void* src) {
    asm volatile("cp.async.cg.shared.global [%0], [%1], 16;"
                 :: "r"(dst_smem), "l"(src));
}
#define CP_COMMIT() asm volatile("cp.async.commit_group;" ::: "memory")
#define CP_WAIT(n)  asm volatile("cp.async.wait_group %0;" :: "n"(n) : "memory")

#define SMS 72                        // smem row stride (halves): conflict-free
#define ABUF_H  (128 * SMS)           // halves per A (or B) tile
#define STAGE_H (2 * ABUF_H)          // A + B per stage
#define GEMM_SMEM (2 * STAGE_H * 2)   // 2 stages, bytes = 73728

// ---------------------------------------------------------------------------
// Kernel 0: convert x + 4 weight matrices to half.
// ---------------------------------------------------------------------------
__global__ __launch_bounds__(256) void tohalf_kernel(
    const float* __restrict__ x,  const float* __restrict__ Wq,
    const float* __restrict__ Wk, const float* __restrict__ Wv,
    const float* __restrict__ Wo)
{
    const float* src; __half* dst; int n4;
    switch (blockIdx.y) {
        case 0: src = x;  dst = g_Xh;  n4 = BT * DIM_ / 4;   break;
        case 1: src = Wq; dst = g_Wqh; n4 = DIM_ * DIM_ / 4; break;
        case 2: src = Wk; dst = g_Wkh; n4 = DIM_ * DIM_ / 4; break;
        case 3: src = Wv; dst = g_Wvh; n4 = DIM_ * DIM_ / 4; break;
        default: src = Wo; dst = g_Woh; n4 = DIM_ * DIM_ / 4; break;
    }
    for (int i = blockIdx.x * 256 + threadIdx.x; i < n4; i += gridDim.x * 256) {
        float4 v = ((const float4*)src)[i];
        *(uint2*)&dst[(size_t)i * 4] =
            make_uint2(pack_h2(v.x, v.y), pack_h2(v.z, v.w));
    }
}

// ---------------------------------------------------------------------------
// Kernel 1: QKV projection. half inputs, cp.async 2-stage, ldmatrix frags,
// BK=64, CTA 128x128, 8 warps of 32x64. RoPE fused in epilogue.
// ---------------------------------------------------------------------------
__global__ __launch_bounds__(256, 2) void qkv_f16()
{
    extern __shared__ char smraw[];
    const uint32_t sm0 = (uint32_t)__cvta_generic_to_shared(smraw);

    const int tid  = threadIdx.x;
    const int lane = tid & 31;
    const int wid  = tid >> 5;
    const int lq   = lane >> 2;
    const int lr   = lane & 3;
    const int wm   = (wid & 3) * 32;
    const int wn   = (wid >> 2) * 64;
    const int m0   = blockIdx.x * 128;
    const int n0   = blockIdx.y * 128;
    const int z    = blockIdx.z;

    const __half* __restrict__ Ah = g_Xh;
    const __half* __restrict__ Bh = (z == 0) ? g_Wqh : (z == 1 ? g_Wkh : g_Wvh);

    // ldmatrix lane address components
    const int ar = (lane & 7) + ((lane & 8) ? 8 : 0);    // A row offset
    const int ac = (lane & 16) ? 8 : 0;                  // A col offset
    const int br = (lane & 7) + ((lane & 16) ? 8 : 0);   // B row offset
    const int bc = (lane & 8) ? 8 : 0;                   // B col offset

    const int crow = tid >> 3;          // 0..31  (cp.async row base)
    const int cc8  = (tid & 7) * 8;     // 0..56

    auto issue = [&](int k0, int buf) {
        uint32_t ab = sm0 + buf * STAGE_H * 2;
        uint32_t bb = ab + ABUF_H * 2;
#pragma unroll
        for (int i = 0; i < 4; i++) {
            int row = crow + i * 32;
            cp16(ab + (row * SMS + cc8) * 2, Ah + (size_t)(m0 + row) * DIM_ + k0 + cc8);
            cp16(bb + (row * SMS + cc8) * 2, Bh + (size_t)(n0 + row) * DIM_ + k0 + cc8);
        }
    };

    float acc[2][8][4];
#pragma unroll
    for (int i = 0; i < 2; i++)
#pragma unroll
        for (int j = 0; j < 8; j++)
#pragma unroll
            for (int v = 0; v < 4; v++) acc[i][j][v] = 0.0f;

    issue(0, 0);
    CP_COMMIT();

    for (int it = 0; it < DIM_ / 64; it++) {
        const int cur = it & 1;
        if (it + 1 < DIM_ / 64) {
            issue((it + 1) * 64, cur ^ 1);
            CP_COMMIT();
            CP_WAIT(1);
        } else {
            CP_WAIT(0);
        }
        __syncthreads();

        const uint32_t ab = sm0 + cur * STAGE_H * 2;
        const uint32_t bb = ab + ABUF_H * 2;

#pragma unroll
        for (int ks = 0; ks < 4; ks++) {
            uint32_t a[2][4];
#pragma unroll
            for (int i = 0; i < 2; i++)
                ldsm4(a[i][0], a[i][1], a[i][2], a[i][3],
                      ab + ((wm + i * 16 + ar) * SMS + ks * 16 + ac) * 2);
#pragma unroll
            for (int jp = 0; jp < 4; jp++) {
                uint32_t b0, b1, b2, b3;
                ldsm4(b0, b1, b2, b3,
                      bb + ((wn + jp * 16 + br) * SMS + ks * 16 + bc) * 2);
                mma_f16(acc[0][2 * jp],     a[0], b0, b1);
                mma_f16(acc[0][2 * jp + 1], a[0], b2, b3);
                mma_f16(acc[1][2 * jp],     a[1], b0, b1);
                mma_f16(acc[1][2 * jp + 1], a[1], b2, b3);
            }
        }
        __syncthreads();
    }

    // ---- Epilogue ----
    if (z < 2) {
        const float C32 = 13.287712379549449f / 32.0f;
        float fr[4][2];
#pragma unroll
        for (int jl = 0; jl < 4; jl++) {
            fr[jl][0] = exp2f(-(float)(jl * 8 + 2 * lr) * C32);
            fr[jl][1] = exp2f(-(float)(jl * 8 + 2 * lr + 1) * C32);
        }
        const float qs = (z == 0) ? 0.125f : 1.0f;
        __half* __restrict__ outp = (z == 0) ? g_Qh : g_Kh;

#pragma unroll
        for (int i = 0; i < 2; i++) {
#pragma unroll
            for (int half_ = 0; half_ < 2; half_++) {
                int row = m0 + wm + i * 16 + lq + 8 * half_;
                int bb2 = row >> 11;
                int t   = row & (TLEN - 1);
                float tf = (float)t;
#pragma unroll
                for (int jl = 0; jl < 4; jl++) {
                    int ncol = n0 + wn + jl * 8 + 2 * lr;
                    int head = ncol >> 6;
                    int hd1  = ncol & 63;     // < 32
                    float o1[2], o2[2];
#pragma unroll
                    for (int v = 0; v < 2; v++) {
                        float s, c;
                        sincosf(tf * fr[jl][v], &s, &c);
                        float q1 = acc[i][jl][2 * half_ + v];
                        float q2 = acc[i][jl + 4][2 * half_ + v];
                        o1[v] = (q1 * c - q2 * s) * qs;
                        o2[v] = (q2 * c + q1 * s) * qs;
                    }
                    size_t base = (((size_t)(bb2 * NH + head)) * TLEN + t) * HDIM;
                    *(__half2*)&outp[base + hd1] = __floats2half2_rn(o1[0], o1[1]);
                    *(__half2*)&outp[base + hd1 + 32] = __floats2half2_rn(o2[0], o2[1]);
                }
            }
        }
    } else {
#pragma unroll
        for (int i = 0; i < 2; i++) {
#pragma unroll
            for (int half_ = 0; half_ < 2; half_++) {
                int row = m0 + wm + i * 16 + lq + 8 * half_;
                int bb2 = row >> 11;
                int t   = row & (TLEN - 1);
#pragma unroll
                for (int j = 0; j < 8; j++) {
                    int ncol = n0 + wn + j * 8 + 2 * lr;
                    int head = ncol >> 6;
                    int hd   = ncol & 63;
                    size_t base = ((size_t)(bb2 * NH + head) * HDIM + hd) * TLEN + t;
                    g_Vh[base]        = __float2half(acc[i][j][2 * half_]);
                    g_Vh[base + TLEN] = __float2half(acc[i][j][2 * half_ + 1]);
                }
            }
        }
    }
}

// ---------------------------------------------------------------------------
// Kernel 2: flash attention. cp.async double-buffered K/V, ldmatrix frags.
// ---------------------------------------------------------------------------
#define VH_STRIDE 136
#define KBUF_H  (128 * SMS)
#define VBUF_H  (64 * VH_STRIDE)
#define ATTN_SMEM (2 * KBUF_H * 2 + 2 * VBUF_H * 2 + TLEN * 4)

__global__ __launch_bounds__(256) void attn_mma(const int* __restrict__ mask)
{
    extern __shared__ char smraw[];
    float* madds = (float*)(smraw + 2 * KBUF_H * 2 + 2 * VBUF_H * 2);
    const uint32_t ks_base = (uint32_t)__cvta_generic_to_shared(smraw);
    const uint32_t vh_base = ks_base + 2 * KBUF_H * 2;

    const int tid  = threadIdx.x;
    const int lane = tid & 31;
    const int wid  = tid >> 5;
    const int lq   = lane >> 2;
    const int lr   = lane & 3;
    const int qt   = blockIdx.x;
    const int bh   = blockIdx.y;
    const int bb   = bh >> 4;
    const int q0   = qt * 128 + wid * 16;

    const __half* __restrict__ Qg = g_Qh + ((size_t)bh * TLEN + q0) * HDIM;
    const __half* __restrict__ Kg = g_Kh + (size_t)bh * TLEN * HDIM;
    const __half* __restrict__ Vg = g_Vh + (size_t)bh * HDIM * TLEN;
    const int*    __restrict__ mrow = mask + (size_t)bb * TLEN;

    // B-frag ldmatrix address components (rows=n/d, cols=k)
    const int br = (lane & 7) + ((lane & 16) ? 8 : 0);
    const int bc = (lane & 8) ? 8 : 0;

    // full-sequence additive mask, computed once
#pragma unroll
    for (int i = 0; i < TLEN / 256; i++)
        madds[tid + i * 256] = (1.0f - (float)mrow[tid + i * 256]) * 1e9f;

    // Q fragments, resident
    uint32_t aq[4][4];
#pragma unroll
    for (int ks = 0; ks < 4; ks++) {
        aq[ks][0] = *(const uint32_t*)&Qg[lq * 64 + ks * 16 + 2 * lr];
        aq[ks][1] = *(const uint32_t*)&Qg[(lq + 8) * 64 + ks * 16 + 2 * lr];
        aq[ks][2] = *(const uint32_t*)&Qg[lq * 64 + ks * 16 + 2 * lr + 8];
        aq[ks][3] = *(const uint32_t*)&Qg[(lq + 8) * 64 + ks * 16 + 2 * lr + 8];
    }

    auto issue_tile = [&](int kt, int buf) {
        uint32_t kdst = ks_base + buf * KBUF_H * 2;
        uint32_t vdst = vh_base + buf * VBUF_H * 2;
#pragma unroll
        for (int i = 0; i < 4; i++) {
            int chunk = tid + i * 256;
            int row = chunk >> 3;
            int c8  = (chunk & 7) * 8;
            cp16(kdst + (row * SMS + c8) * 2,
                 Kg + ((size_t)kt * 128 + row) * 64 + c8);
        }
#pragma unroll
        for (int i = 0; i < 4; i++) {
            int linear = tid + i * 256;
            int d  = linear >> 4;
            int kp = (linear & 15) * 8;
            cp16(vdst + (d * VH_STRIDE + kp) * 2,
                 Vg + (size_t)d * TLEN + kt * 128 + kp);
        }
    };

    float oacc[8][4];
#pragma unroll
    for (int dn = 0; dn < 8; dn++)
#pragma unroll
        for (int v = 0; v < 4; v++) oacc[dn][v] = 0.0f;
    float mA = -1e30f, mB = -1e30f, lA = 0.0f, lB = 0.0f;

    issue_tile(0, 0);
    CP_COMMIT();

    for (int kt = 0; kt < 16; kt++) {
        const int cur = kt & 1;
        if (kt + 1 < 16) {
            issue_tile(kt + 1, cur ^ 1);
            CP_COMMIT();
            CP_WAIT(1);
        } else {
            CP_WAIT(0);
        }
        __syncthreads();

        const uint32_t kb = ks_base + cur * KBUF_H * 2;
        const uint32_t vb = vh_base + cur * VBUF_H * 2;

        // S = Q K^T  (ldmatrix.x4 per (j-pair, ks))
        float sacc[16][4];
#pragma unroll
        for (int j = 0; j < 16; j++)
#pragma unroll
            for (int v = 0; v < 4; v++) sacc[j][v] = 0.0f;

#pragma unroll
        for (int jp = 0; jp < 8; jp++) {
#pragma unroll
            for (int ks = 0; ks < 4; ks++) {
                uint32_t b0, b1, b2, b3;
                ldsm4(b0, b1, b2, b3,
                      kb + ((jp * 16 + br) * SMS + ks * 16 + bc) * 2);
                mma_f16(sacc[2 * jp],     aq[ks], b0, b1);
                mma_f16(sacc[2 * jp + 1], aq[ks], b2, b3);
            }
        }

        // mask + online softmax
        const float* mk = madds + kt * 128;
        float rmaxA = -1e30f, rmaxB = -1e30f;
#pragma unroll
        for (int j = 0; j < 16; j++) {
            float m0v = mk[j * 8 + 2 * lr];
            float m1v = mk[j * 8 + 2 * lr + 1];
            sacc[j][0] -= m0v; sacc[j][1] -= m1v;
            sacc[j][2] -= m0v; sacc[j][3] -= m1v;
            rmaxA = fmaxf(rmaxA, fmaxf(sacc[j][0], sacc[j][1]));
            rmaxB = fmaxf(rmaxB, fmaxf(sacc[j][2], sacc[j][3]));
        }
        rmaxA = fmaxf(rmaxA, __shfl_xor_sync(0xffffffffu, rmaxA, 1));
        rmaxA = fmaxf(rmaxA, __shfl_xor_sync(0xffffffffu, rmaxA, 2));
        rmaxB = fmaxf(rmaxB, __shfl_xor_sync(0xffffffffu, rmaxB, 1));
        rmaxB = fmaxf(rmaxB, __shfl_xor_sync(0xffffffffu, rmaxB, 2));

        float mnA = fmaxf(mA, rmaxA), mnB = fmaxf(mB, rmaxB);
        float cA = __expf(mA - mnA),  cB = __expf(mB - mnB);
        float sumA = 0.0f, sumB = 0.0f;

        uint32_t pa[8][4];
#pragma unroll
        for (int s = 0; s < 8; s++) {
            float p0 = __expf(sacc[2 * s][0] - mnA);
            float p1 = __expf(sacc[2 * s][1] - mnA);
            float p2 = __expf(sacc[2 * s][2] - mnB);
            float p3 = __expf(sacc[2 * s][3] - mnB);
            float p4 = __expf(sacc[2 * s + 1][0] - mnA);
            float p5 = __expf(sacc[2 * s + 1][1] - mnA);
            float p6 = __expf(sacc[2 * s + 1][2] - mnB);
            float p7 = __expf(sacc[2 * s + 1][3] - mnB);
            sumA += p0 + p1 + p4 + p5;
            sumB += p2 + p3 + p6 + p7;
            pa[s][0] = pack_h2(p0, p1);
            pa[s][1] = pack_h2(p2, p3);
            pa[s][2] = pack_h2(p4, p5);
            pa[s][3] = pack_h2(p6, p7);
        }
        sumA += __shfl_xor_sync(0xffffffffu, sumA, 1);
        sumA += __shfl_xor_sync(0xffffffffu, sumA, 2);
        sumB += __shfl_xor_sync(0xffffffffu, sumB, 1);
        sumB += __shfl_xor_sync(0xffffffffu, sumB, 2);

        lA = lA * cA + sumA;  lB = lB * cB + sumB;
        mA = mnA;             mB = mnB;
#pragma unroll
        for (int dn = 0; dn < 8; dn++) {
            oacc[dn][0] *= cA; oacc[dn][1] *= cA;
            oacc[dn][2] *= cB; oacc[dn][3] *= cB;
        }

        // O += P @ V  (ldmatrix.x4 per (d-pair, s))
#pragma unroll
        for (int s = 0; s < 8; s++) {
#pragma unroll
            for (int dp = 0; dp < 4; dp++) {
                uint32_t b0, b1, b2, b3;
                ldsm4(b0, b1, b2, b3,
                      vb + ((dp * 16 + br) * VH_STRIDE + s * 16 + bc) * 2);
                mma_f16(oacc[2 * dp],     pa[s], b0, b1);
                mma_f16(oacc[2 * dp + 1], pa[s], b2, b3);
            }
        }
        __syncthreads();
    }

    // normalize + write half to g_Oh [bt][dim]
    const int head = bh & 15;
    float invA = 1.0f / lA, invB = 1.0f / lB;
    size_t rowA = (size_t)(bb * TLEN + q0 + lq) * DIM_ + head * 64;
    size_t rowB = (size_t)(bb * TLEN + q0 + lq + 8) * DIM_ + head * 64;
#pragma unroll
    for (int dn = 0; dn < 8; dn++) {
        *(__half2*)&g_Oh[rowA + dn * 8 + 2 * lr] =
            __floats2half2_rn(oacc[dn][0] * invA, oacc[dn][1] * invA);
        *(__half2*)&g_Oh[rowB + dn * 8 + 2 * lr] =
            __floats2half2_rn(oacc[dn][2] * invB, oacc[dn][3] * invB);
    }
}

// ---------------------------------------------------------------------------
// Kernel 3: output projection + residual. Same pipeline as qkv.
// ---------------------------------------------------------------------------
__global__ __launch_bounds__(256, 2) void oproj_f16(const float* __restrict__ x)
{
    extern __shared__ char smraw[];
    const uint32_t sm0 = (uint32_t)__cvta_generic_to_shared(smraw);

    const int tid  = threadIdx.x;
    const int lane = tid & 31;
    const int wid  = tid >> 5;
    const int lq   = lane >> 2;
    const int lr   = lane & 3;
    const int wm   = (wid & 3) * 32;
    const int wn   = (wid >> 2) * 64;
    const int m0   = blockIdx.x * 128;
    const int n0   = blockIdx.y * 128;

    const __half* __restrict__ Ah = g_Oh;
    const __half* __restrict__ Bh = g_Woh;

    const int ar = (lane & 7) + ((lane & 8) ? 8 : 0);
    const int ac = (lane & 16) ? 8 : 0;
    const int br = (lane & 7) + ((lane & 16) ? 8 : 0);
    const int bc = (lane & 8) ? 8 : 0;

    const int crow = tid >> 3;
    const int cc8  = (tid & 7) * 8;

    auto issue = [&](int k0, int buf) {
        uint32_t ab = sm0 + buf * STAGE_H * 2;
        uint32_t bb = ab + ABUF_H * 2;
#pragma unroll
        for (int i = 0; i < 4; i++) {
            int row = crow + i * 32;
            cp16(ab + (row * SMS + cc8) * 2, Ah + (size_t)(m0 + row) * DIM_ + k0 + cc8);
            cp16(bb + (row * SMS + cc8) * 2, Bh + (size_t)(n0 + row) * DIM_ + k0 + cc8);
        }
    };

    float acc[2][8][4];
#pragma unroll
    for (int i = 0; i < 2; i++)
#pragma unroll
        for (int j = 0; j < 8; j++)
#pragma unroll
            for (int v = 0; v < 4; v++) acc[i][j][v] = 0.0f;

    issue(0, 0);
    CP_COMMIT();

    for (int it = 0; it < DIM_ / 64; it++) {
        const int cur = it & 1;
        if (it + 1 < DIM_ / 64) {
            issue((it + 1) * 64, cur ^ 1);
            CP_COMMIT();
            CP_WAIT(1);
        } else {
            CP_WAIT(0);
        }
        __syncthreads();

        const uint32_t ab = sm0 + cur * STAGE_H * 2;
        const uint32_t bb = ab + ABUF_H * 2;

#pragma unroll
        for (int ks = 0; ks < 4; ks++) {
            uint32_t a[2][4];
#pragma unroll
            for (int i = 0; i < 2; i++)
                ldsm4(a[i][0], a[i][1], a[i][2], a[i][3],
                      ab + ((wm + i * 16 + ar) * SMS + ks * 16 + ac) * 2);
#pragma unroll
            for (int jp = 0; jp < 4; jp++) {
                uint32_t b0, b1, b2, b3;
                ldsm4(b0, b1, b2, b3,
                      bb + ((wn + jp * 16 + br) * SMS + ks * 16 + bc) * 2);
                mma_f16(acc[0][2 * jp],     a[0], b0, b1);
                mma_f16(acc[0][2 * jp + 1], a[0], b2, b3);
                mma_f16(acc[1][2 * jp],     a[1], b0, b1);
                mma_f16(acc[1][2 * jp + 1], a[1], b2, b3);
            }
        }
        __syncthreads();
    }

    // Epilogue: h = x + proj -> g_Hh
#pragma unroll
    for (int i = 0; i < 2; i++) {
#pragma unroll
        for (int half_ = 0; half_ < 2; half_++) {
            int row = m0 + wm + i * 16 + lq + 8 * half_;
#pragma unroll
            for (int j = 0; j < 8; j++) {
                int ncol = n0 + wn + j * 8 + 2 * lr;
                size_t idx = (size_t)row * DIM_ + ncol;
                float2 xr = *(const float2*)(x + idx);
                *(float2*)(g_Hh + idx) =
                    make_float2(acc[i][j][2 * half_] + xr.x,
                                acc[i][j][2 * half_ + 1] + xr.y);
            }
        }
    }
}

// ---------------------------------------------------------------------------
// Kernel 4: LayerNorm per row of h.
// ---------------------------------------------------------------------------
__global__ __launch_bounds__(256) void ln_kernel(
    const float* __restrict__ gamma,
    const float* __restrict__ beta,
    float* __restrict__ out)
{
    __shared__ float red0[8];
    __shared__ float red1[8];
    const int row = blockIdx.x;
    const int tid = threadIdx.x;
    const float* hr = g_Hh + (size_t)row * DIM_;

    float4 v = *(const float4*)(hr + tid * 4);
    float sum = v.x + v.y + v.z + v.w;
    float sq  = v.x * v.x + v.y * v.y + v.z * v.z + v.w * v.w;
#pragma unroll
    for (int off = 16; off; off >>= 1) {
        sum += __shfl_xor_sync(0xffffffffu, sum, off);
        sq  += __shfl_xor_sync(0xffffffffu, sq, off);
    }
    int wid = tid >> 5, lane = tid & 31;
    if (lane == 0) { red0[wid] = sum; red1[wid] = sq; }
    __syncthreads();

    float tot = 0.0f, totsq = 0.0f;
#pragma unroll
    for (int w = 0; w < 8; w++) { tot += red0[w]; totsq += red1[w]; }

    float mu = tot * (1.0f / DIM_);
    float var = totsq * (1.0f / DIM_) - mu * mu;
    float rs = rsqrtf(var + 1e-5f);

    int e = tid * 4;
    float4 g  = *(const float4*)(gamma + e);
    float4 be = *(const float4*)(beta + e);
    float4 r = make_float4((v.x - mu) * rs * g.x + be.x,
                           (v.y - mu) * rs * g.y + be.y,
                           (v.z - mu) * rs * g.z + be.z,
                           (v.w - mu) * rs * g.w + be.w);
    *(float4*)(out + (size_t)row * DIM_ + e) = r;
}

// ---------------------------------------------------------------------------
extern "C" void kernel_launch(void* const* d_in, const int* in_sizes, int n_in,
                              void* d_out, int out_size)
{
    const float* x     = (const float*)d_in[0];
    const int*   mask  = (const int*)d_in[1];
    const float* Wq    = (const float*)d_in[2];
    const float* Wk    = (const float*)d_in[3];
    const float* Wv    = (const float*)d_in[4];
    const float* Wo    = (const float*)d_in[5];
    const float* gamma = (const float*)d_in[6];
    const float* beta  = (const float*)d_in[7];
    float* out = (float*)d_out;

    cudaFuncSetAttribute(qkv_f16,
                         cudaFuncAttributeMaxDynamicSharedMemorySize, GEMM_SMEM);
    cudaFuncSetAttribute(oproj_f16,
                         cudaFuncAttributeMaxDynamicSharedMemorySize, GEMM_SMEM);
    cudaFuncSetAttribute(attn_mma,
                         cudaFuncAttributeMaxDynamicSharedMemorySize, ATTN_SMEM);

    tohalf_kernel<<<dim3(2048, 5), 256>>>(x, Wq, Wk, Wv, Wo);

    qkv_f16<<<dim3(BT / 128, DIM_ / 128, 3), 256, GEMM_SMEM>>>();

    attn_mma<<<dim3(TLEN / 128, BSZ * NH), 256, ATTN_SMEM>>>(mask);

    oproj_f16<<<dim3(BT / 128, DIM_ / 128), 256, GEMM_SMEM>>>(x);

    ln_kernel<<<BT, 256>>>(gamma, beta, out);
}

// round 13
// speedup vs baseline: 1.3170x; 1.3170x over previous
#include <cuda_runtime.h>
#include <cuda_fp16.h>
#include <math.h>
#include <stddef.h>
#include <stdint.h>

#define BSZ   4
#define TLEN  2048
#define DIM_  1024
#define NH    16
#define HDIM  64
#define BT    (BSZ * TLEN)        // 8192

// Scratch (device-global; no runtime allocation)
__device__ __half g_Xh [(size_t)BT * DIM_];               // x in half
__device__ __half g_Wqh[(size_t)DIM_ * DIM_];
__device__ __half g_Wkh[(size_t)DIM_ * DIM_];
__device__ __half g_Wvh[(size_t)DIM_ * DIM_];
__device__ __half g_Woh[(size_t)DIM_ * DIM_];
__device__ __half g_Qh[(size_t)BSZ * NH * TLEN * HDIM];   // [bh][t][d], rope+scale
__device__ __half g_Kh[(size_t)BSZ * NH * TLEN * HDIM];   // [bh][t][d], rope
__device__ __half g_Vh[(size_t)BSZ * NH * HDIM * TLEN];   // [bh][d][t]
__device__ __half g_Oh[(size_t)BT * DIM_];                // [bt][dim] attention out
__device__ float  g_Hh[(size_t)BT * DIM_];                // residual sum

// ---------------------------------------------------------------------------
// helpers
// ---------------------------------------------------------------------------
__device__ __forceinline__ void mma_f16(float c[4],
                                        const uint32_t a[4],
                                        uint32_t b0, uint32_t b1) {
    asm volatile(
        "mma.sync.aligned.m16n8k16.row.col.f32.f16.f16.f32 "
        "{%0,%1,%2,%3},{%4,%5,%6,%7},{%8,%9},{%0,%1,%2,%3};"
        : "+f"(c[0]), "+f"(c[1]), "+f"(c[2]), "+f"(c[3])
        : "r"(a[0]), "r"(a[1]), "r"(a[2]), "r"(a[3]),
          "r"(b0), "r"(b1));
}

__device__ __forceinline__ uint32_t pack_h2(float lo, float hi) {
    __half2 h = __floats2half2_rn(lo, hi);
    return *(uint32_t*)&h;
}

__device__ __forceinline__ void cp16(uint32_t dst_smem, const void* src) {
    asm volatile("cp.async.cg.shared.global [%0], [%1], 16;"
                 :: "r"(dst_smem), "l"(src));
}
#define CP_COMMIT() asm volatile("cp.async.commit_group;" ::: "memory")
#define CP_WAIT(n)  asm volatile("cp.async.wait_group %0;" :: "n"(n) : "memory")

#define SMS 72   // smem row stride in halves (conflict-free frags)

// ---------------------------------------------------------------------------
// Kernel 0: convert x + 4 weight matrices to half (one-time, ~72MB traffic).
// ---------------------------------------------------------------------------
__global__ __launch_bounds__(256) void tohalf_kernel(
    const float* __restrict__ x,  const float* __restrict__ Wq,
    const float* __restrict__ Wk, const float* __restrict__ Wv,
    const float* __restrict__ Wo)
{
    const float* src; __half* dst; int n4;
    switch (blockIdx.y) {
        case 0: src = x;  dst = g_Xh;  n4 = BT * DIM_ / 4;   break;
        case 1: src = Wq; dst = g_Wqh; n4 = DIM_ * DIM_ / 4; break;
        case 2: src = Wk; dst = g_Wkh; n4 = DIM_ * DIM_ / 4; break;
        case 3: src = Wv; dst = g_Wvh; n4 = DIM_ * DIM_ / 4; break;
        default: src = Wo; dst = g_Woh; n4 = DIM_ * DIM_ / 4; break;
    }
    for (int i = blockIdx.x * 256 + threadIdx.x; i < n4; i += gridDim.x * 256) {
        float4 v = ((const float4*)src)[i];
        *(uint2*)&dst[(size_t)i * 4] =
            make_uint2(pack_h2(v.x, v.y), pack_h2(v.z, v.w));
    }
}

// ---------------------------------------------------------------------------
// Kernel 1: QKV projection. R8 register-prefetch pipeline, half inputs.
// CTA 128x128, BK=32, 8 warps of 32x64. RoPE fused in epilogue.
// ---------------------------------------------------------------------------
__global__ __launch_bounds__(256, 2) void qkv_f16()
{
    __shared__ __half As[128][SMS];
    __shared__ __half Bs[128][SMS];

    const int tid  = threadIdx.x;
    const int lane = tid & 31;
    const int wid  = tid >> 5;
    const int lq   = lane >> 2;
    const int lr   = lane & 3;
    const int wm   = (wid & 3) * 32;
    const int wn   = (wid >> 2) * 64;
    const int m0   = blockIdx.x * 128;
    const int n0   = blockIdx.y * 128;
    const int z    = blockIdx.z;

    const __half* __restrict__ Ah = g_Xh;
    const __half* __restrict__ Bh = (z == 0) ? g_Wqh : (z == 1 ? g_Wkh : g_Wvh);

    const int arow = tid >> 2;          // 0..63
    const int ac8  = (tid & 3) * 8;     // 0,8,16,24

    float acc[2][8][4];
#pragma unroll
    for (int i = 0; i < 2; i++)
#pragma unroll
        for (int j = 0; j < 8; j++)
#pragma unroll
            for (int v = 0; v < 4; v++) acc[i][j][v] = 0.0f;

    uint4 la[2], lb[2];
    // prologue: tile k0=0 into registers
#pragma unroll
    for (int r = 0; r < 2; r++) {
        la[r] = *(const uint4*)(Ah + (size_t)(m0 + arow + 64 * r) * DIM_ + ac8);
        lb[r] = *(const uint4*)(Bh + (size_t)(n0 + arow + 64 * r) * DIM_ + ac8);
    }

    for (int k0 = 0; k0 < DIM_; k0 += 32) {
        __syncthreads();
#pragma unroll
        for (int r = 0; r < 2; r++) {
            *(uint4*)&As[arow + 64 * r][ac8] = la[r];
            *(uint4*)&Bs[arow + 64 * r][ac8] = lb[r];
        }
        __syncthreads();

        // prefetch next tile (overlaps the mma block)
        if (k0 + 32 < DIM_) {
            int kn = k0 + 32;
#pragma unroll
            for (int r = 0; r < 2; r++) {
                la[r] = *(const uint4*)(Ah + (size_t)(m0 + arow + 64 * r) * DIM_ + kn + ac8);
                lb[r] = *(const uint4*)(Bh + (size_t)(n0 + arow + 64 * r) * DIM_ + kn + ac8);
            }
        }

#pragma unroll
        for (int ks = 0; ks < 32; ks += 16) {
            uint32_t a[2][4];
#pragma unroll
            for (int i = 0; i < 2; i++) {
                a[i][0] = *(const uint32_t*)&As[wm + i * 16 + lq][ks + 2 * lr];
                a[i][1] = *(const uint32_t*)&As[wm + i * 16 + 8 + lq][ks + 2 * lr];
                a[i][2] = *(const uint32_t*)&As[wm + i * 16 + lq][ks + 2 * lr + 8];
                a[i][3] = *(const uint32_t*)&As[wm + i * 16 + 8 + lq][ks + 2 * lr + 8];
            }
#pragma unroll
            for (int j = 0; j < 8; j++) {
                uint32_t b0 = *(const uint32_t*)&Bs[wn + j * 8 + lq][ks + 2 * lr];
                uint32_t b1 = *(const uint32_t*)&Bs[wn + j * 8 + lq][ks + 2 * lr + 8];
#pragma unroll
                for (int i = 0; i < 2; i++)
                    mma_f16(acc[i][j], a[i], b0, b1);
            }
        }
    }

    // ---- Epilogue ----
    if (z < 2) {
        const float C32 = 13.287712379549449f / 32.0f;
        float fr[4][2];
#pragma unroll
        for (int jl = 0; jl < 4; jl++) {
            fr[jl][0] = exp2f(-(float)(jl * 8 + 2 * lr) * C32);
            fr[jl][1] = exp2f(-(float)(jl * 8 + 2 * lr + 1) * C32);
        }
        const float qs = (z == 0) ? 0.125f : 1.0f;
        __half* __restrict__ outp = (z == 0) ? g_Qh : g_Kh;

#pragma unroll
        for (int i = 0; i < 2; i++) {
#pragma unroll
            for (int half_ = 0; half_ < 2; half_++) {
                int row = m0 + wm + i * 16 + lq + 8 * half_;
                int bb2 = row >> 11;
                int t   = row & (TLEN - 1);
                float tf = (float)t;
#pragma unroll
                for (int jl = 0; jl < 4; jl++) {
                    int ncol = n0 + wn + jl * 8 + 2 * lr;
                    int head = ncol >> 6;
                    int hd1  = ncol & 63;     // < 32
                    float o1[2], o2[2];
#pragma unroll
                    for (int v = 0; v < 2; v++) {
                        float s, c;
                        sincosf(tf * fr[jl][v], &s, &c);
                        float q1 = acc[i][jl][2 * half_ + v];
                        float q2 = acc[i][jl + 4][2 * half_ + v];
                        o1[v] = (q1 * c - q2 * s) * qs;
                        o2[v] = (q2 * c + q1 * s) * qs;
                    }
                    size_t base = (((size_t)(bb2 * NH + head)) * TLEN + t) * HDIM;
                    *(__half2*)&outp[base + hd1] = __floats2half2_rn(o1[0], o1[1]);
                    *(__half2*)&outp[base + hd1 + 32] = __floats2half2_rn(o2[0], o2[1]);
                }
            }
        }
    } else {
#pragma unroll
        for (int i = 0; i < 2; i++) {
#pragma unroll
            for (int half_ = 0; half_ < 2; half_++) {
                int row = m0 + wm + i * 16 + lq + 8 * half_;
                int bb2 = row >> 11;
                int t   = row & (TLEN - 1);
#pragma unroll
                for (int j = 0; j < 8; j++) {
                    int ncol = n0 + wn + j * 8 + 2 * lr;
                    int head = ncol >> 6;
                    int hd   = ncol & 63;
                    size_t base = ((size_t)(bb2 * NH + head) * HDIM + hd) * TLEN + t;
                    g_Vh[base]        = __float2half(acc[i][j][2 * half_]);
                    g_Vh[base + TLEN] = __float2half(acc[i][j][2 * half_ + 1]);
                }
            }
        }
    }
}

// ---------------------------------------------------------------------------
// Kernel 2: flash attention (identical to R8 best).
// ---------------------------------------------------------------------------
#define VH_STRIDE 136
#define KBUF_H  (128 * SMS)
#define VBUF_H  (64 * VH_STRIDE)
#define ATTN_SMEM (2 * KBUF_H * 2 + 2 * VBUF_H * 2 + TLEN * 4)

__global__ __launch_bounds__(256) void attn_mma(const int* __restrict__ mask)
{
    extern __shared__ char smraw[];
    float* madds = (float*)(smraw + 2 * KBUF_H * 2 + 2 * VBUF_H * 2);
    const uint32_t ks_base = (uint32_t)__cvta_generic_to_shared(smraw);
    const uint32_t vh_base = ks_base + 2 * KBUF_H * 2;
    __half* Ks0 = (__half*)smraw;
    __half* Vh0 = (__half*)(smraw + 2 * KBUF_H * 2);

    const int tid  = threadIdx.x;
    const int lane = tid & 31;
    const int wid  = tid >> 5;
    const int lq   = lane >> 2;
    const int lr   = lane & 3;
    const int qt   = blockIdx.x;
    const int bh   = blockIdx.y;
    const int bb   = bh >> 4;
    const int q0   = qt * 128 + wid * 16;

    const __half* __restrict__ Qg = g_Qh + ((size_t)bh * TLEN + q0) * HDIM;
    const __half* __restrict__ Kg = g_Kh + (size_t)bh * TLEN * HDIM;
    const __half* __restrict__ Vg = g_Vh + (size_t)bh * HDIM * TLEN;
    const int*    __restrict__ mrow = mask + (size_t)bb * TLEN;

#pragma unroll
    for (int i = 0; i < TLEN / 256; i++)
        madds[tid + i * 256] = (1.0f - (float)mrow[tid + i * 256]) * 1e9f;

    uint32_t aq[4][4];
#pragma unroll
    for (int ks = 0; ks < 4; ks++) {
        aq[ks][0] = *(const uint32_t*)&Qg[lq * 64 + ks * 16 + 2 * lr];
        aq[ks][1] = *(const uint32_t*)&Qg[(lq + 8) * 64 + ks * 16 + 2 * lr];
        aq[ks][2] = *(const uint32_t*)&Qg[lq * 64 + ks * 16 + 2 * lr + 8];
        aq[ks][3] = *(const uint32_t*)&Qg[(lq + 8) * 64 + ks * 16 + 2 * lr + 8];
    }

    auto issue_tile = [&](int kt, int buf) {
        uint32_t kdst = ks_base + buf * KBUF_H * 2;
        uint32_t vdst = vh_base + buf * VBUF_H * 2;
#pragma unroll
        for (int i = 0; i < 4; i++) {
            int chunk = tid + i * 256;
            int row = chunk >> 3;
            int c8  = (chunk & 7) * 8;
            cp16(kdst + (row * SMS + c8) * 2,
                 Kg + ((size_t)kt * 128 + row) * 64 + c8);
        }
#pragma unroll
        for (int i = 0; i < 4; i++) {
            int linear = tid + i * 256;
            int d  = linear >> 4;
            int kp = (linear & 15) * 8;
            cp16(vdst + (d * VH_STRIDE + kp) * 2,
                 Vg + (size_t)d * TLEN + kt * 128 + kp);
        }
    };

    float oacc[8][4];
#pragma unroll
    for (int dn = 0; dn < 8; dn++)
#pragma unroll
        for (int v = 0; v < 4; v++) oacc[dn][v] = 0.0f;
    float mA = -1e30f, mB = -1e30f, lA = 0.0f, lB = 0.0f;

    issue_tile(0, 0);
    CP_COMMIT();

    for (int kt = 0; kt < 16; kt++) {
        const int cur = kt & 1;
        if (kt + 1 < 16) {
            issue_tile(kt + 1, cur ^ 1);
            CP_COMMIT();
            CP_WAIT(1);
        } else {
            CP_WAIT(0);
        }
        __syncthreads();

        const __half* Kb = Ks0 + cur * KBUF_H;
        const __half* Vb = Vh0 + cur * VBUF_H;

        float sacc[16][4];
#pragma unroll
        for (int j = 0; j < 16; j++)
#pragma unroll
            for (int v = 0; v < 4; v++) sacc[j][v] = 0.0f;

#pragma unroll
        for (int j = 0; j < 16; j++) {
#pragma unroll
            for (int ks = 0; ks < 4; ks++) {
                uint32_t b0 = *(const uint32_t*)&Kb[(j * 8 + lq) * SMS + ks * 16 + 2 * lr];
                uint32_t b1 = *(const uint32_t*)&Kb[(j * 8 + lq) * SMS + ks * 16 + 2 * lr + 8];
                mma_f16(sacc[j], aq[ks], b0, b1);
            }
        }

        const float* mk = madds + kt * 128;
        float rmaxA = -1e30f, rmaxB = -1e30f;
#pragma unroll
        for (int j = 0; j < 16; j++) {
            float m0v = mk[j * 8 + 2 * lr];
            float m1v = mk[j * 8 + 2 * lr + 1];
            sacc[j][0] -= m0v; sacc[j][1] -= m1v;
            sacc[j][2] -= m0v; sacc[j][3] -= m1v;
            rmaxA = fmaxf(rmaxA, fmaxf(sacc[j][0], sacc[j][1]));
            rmaxB = fmaxf(rmaxB, fmaxf(sacc[j][2], sacc[j][3]));
        }
        rmaxA = fmaxf(rmaxA, __shfl_xor_sync(0xffffffffu, rmaxA, 1));
        rmaxA = fmaxf(rmaxA, __shfl_xor_sync(0xffffffffu, rmaxA, 2));
        rmaxB = fmaxf(rmaxB, __shfl_xor_sync(0xffffffffu, rmaxB, 1));
        rmaxB = fmaxf(rmaxB, __shfl_xor_sync(0xffffffffu, rmaxB, 2));

        float mnA = fmaxf(mA, rmaxA), mnB = fmaxf(mB, rmaxB);
        float cA = __expf(mA - mnA),  cB = __expf(mB - mnB);
        float sumA = 0.0f, sumB = 0.0f;

        uint32_t pa[8][4];
#pragma unroll
        for (int s = 0; s < 8; s++) {
            float p0 = __expf(sacc[2 * s][0] - mnA);
            float p1 = __expf(sacc[2 * s][1] - mnA);
            float p2 = __expf(sacc[2 * s][2] - mnB);
            float p3 = __expf(sacc[2 * s][3] - mnB);
            float p4 = __expf(sacc[2 * s + 1][0] - mnA);
            float p5 = __expf(sacc[2 * s + 1][1] - mnA);
            float p6 = __expf(sacc[2 * s + 1][2] - mnB);
            float p7 = __expf(sacc[2 * s + 1][3] - mnB);
            sumA += p0 + p1 + p4 + p5;
            sumB += p2 + p3 + p6 + p7;
            pa[s][0] = pack_h2(p0, p1);
            pa[s][1] = pack_h2(p2, p3);
            pa[s][2] = pack_h2(p4, p5);
            pa[s][3] = pack_h2(p6, p7);
        }
        sumA += __shfl_xor_sync(0xffffffffu, sumA, 1);
        sumA += __shfl_xor_sync(0xffffffffu, sumA, 2);
        sumB += __shfl_xor_sync(0xffffffffu, sumB, 1);
        sumB += __shfl_xor_sync(0xffffffffu, sumB, 2);

        lA = lA * cA + sumA;  lB = lB * cB + sumB;
        mA = mnA;             mB = mnB;
#pragma unroll
        for (int dn = 0; dn < 8; dn++) {
            oacc[dn][0] *= cA; oacc[dn][1] *= cA;
            oacc[dn][2] *= cB; oacc[dn][3] *= cB;
        }

#pragma unroll
        for (int s = 0; s < 8; s++) {
#pragma unroll
            for (int dn = 0; dn < 8; dn++) {
                const __half* vb = &Vb[(dn * 8 + lq) * VH_STRIDE + s * 16 + 2 * lr];
                uint32_t b0 = *(const uint32_t*)vb;
                uint32_t b1 = *(const uint32_t*)(vb + 8);
                mma_f16(oacc[dn], pa[s], b0, b1);
            }
        }
        __syncthreads();
    }

    const int head = bh & 15;
    float invA = 1.0f / lA, invB = 1.0f / lB;
    size_t rowA = (size_t)(bb * TLEN + q0 + lq) * DIM_ + head * 64;
    size_t rowB = (size_t)(bb * TLEN + q0 + lq + 8) * DIM_ + head * 64;
#pragma unroll
    for (int dn = 0; dn < 8; dn++) {
        *(__half2*)&g_Oh[rowA + dn * 8 + 2 * lr] =
            __floats2half2_rn(oacc[dn][0] * invA, oacc[dn][1] * invA);
        *(__half2*)&g_Oh[rowB + dn * 8 + 2 * lr] =
            __floats2half2_rn(oacc[dn][2] * invB, oacc[dn][3] * invB);
    }
}

// ---------------------------------------------------------------------------
// Kernel 3: output projection + residual. R8 pipeline, half inputs.
// ---------------------------------------------------------------------------
__global__ __launch_bounds__(256, 2) void oproj_f16(const float* __restrict__ x)
{
    __shared__ __half As[128][SMS];
    __shared__ __half Bs[128][SMS];

    const int tid  = threadIdx.x;
    const int lane = tid & 31;
    const int wid  = tid >> 5;
    const int lq   = lane >> 2;
    const int lr   = lane & 3;
    const int wm   = (wid & 3) * 32;
    const int wn   = (wid >> 2) * 64;
    const int m0   = blockIdx.x * 128;
    const int n0   = blockIdx.y * 128;

    const __half* __restrict__ Ah = g_Oh;
    const __half* __restrict__ Bh = g_Woh;

    const int arow = tid >> 2;
    const int ac8  = (tid & 3) * 8;

    float acc[2][8][4];
#pragma unroll
    for (int i = 0; i < 2; i++)
#pragma unroll
        for (int j = 0; j < 8; j++)
#pragma unroll
            for (int v = 0; v < 4; v++) acc[i][j][v] = 0.0f;

    uint4 la[2], lb[2];
#pragma unroll
    for (int r = 0; r < 2; r++) {
        la[r] = *(const uint4*)(Ah + (size_t)(m0 + arow + 64 * r) * DIM_ + ac8);
        lb[r] = *(const uint4*)(Bh + (size_t)(n0 + arow + 64 * r) * DIM_ + ac8);
    }

    for (int k0 = 0; k0 < DIM_; k0 += 32) {
        __syncthreads();
#pragma unroll
        for (int r = 0; r < 2; r++) {
            *(uint4*)&As[arow + 64 * r][ac8] = la[r];
            *(uint4*)&Bs[arow + 64 * r][ac8] = lb[r];
        }
        __syncthreads();

        if (k0 + 32 < DIM_) {
            int kn = k0 + 32;
#pragma unroll
            for (int r = 0; r < 2; r++) {
                la[r] = *(const uint4*)(Ah + (size_t)(m0 + arow + 64 * r) * DIM_ + kn + ac8);
                lb[r] = *(const uint4*)(Bh + (size_t)(n0 + arow + 64 * r) * DIM_ + kn + ac8);
            }
        }

#pragma unroll
        for (int ks = 0; ks < 32; ks += 16) {
            uint32_t a[2][4];
#pragma unroll
            for (int i = 0; i < 2; i++) {
                a[i][0] = *(const uint32_t*)&As[wm + i * 16 + lq][ks + 2 * lr];
                a[i][1] = *(const uint32_t*)&As[wm + i * 16 + 8 + lq][ks + 2 * lr];
                a[i][2] = *(const uint32_t*)&As[wm + i * 16 + lq][ks + 2 * lr + 8];
                a[i][3] = *(const uint32_t*)&As[wm + i * 16 + 8 + lq][ks + 2 * lr + 8];
            }
#pragma unroll
            for (int j = 0; j < 8; j++) {
                uint32_t b0 = *(const uint32_t*)&Bs[wn + j * 8 + lq][ks + 2 * lr];
                uint32_t b1 = *(const uint32_t*)&Bs[wn + j * 8 + lq][ks + 2 * lr + 8];
#pragma unroll
                for (int i = 0; i < 2; i++)
                    mma_f16(acc[i][j], a[i], b0, b1);
            }
        }
    }

    // Epilogue: h = x + proj -> g_Hh
#pragma unroll
    for (int i = 0; i < 2; i++) {
#pragma unroll
        for (int half_ = 0; half_ < 2; half_++) {
            int row = m0 + wm + i * 16 + lq + 8 * half_;
#pragma unroll
            for (int j = 0; j < 8; j++) {
                int ncol = n0 + wn + j * 8 + 2 * lr;
                size_t idx = (size_t)row * DIM_ + ncol;
                float2 xr = *(const float2*)(x + idx);
                *(float2*)(g_Hh + idx) =
                    make_float2(acc[i][j][2 * half_] + xr.x,
                                acc[i][j][2 * half_ + 1] + xr.y);
            }
        }
    }
}

// ---------------------------------------------------------------------------
// Kernel 4: LayerNorm per row of h.
// ---------------------------------------------------------------------------
__global__ __launch_bounds__(256) void ln_kernel(
    const float* __restrict__ gamma,
    const float* __restrict__ beta,
    float* __restrict__ out)
{
    __shared__ float red0[8];
    __shared__ float red1[8];
    const int row = blockIdx.x;
    const int tid = threadIdx.x;
    const float* hr = g_Hh + (size_t)row * DIM_;

    float4 v = *(const float4*)(hr + tid * 4);
    float sum = v.x + v.y + v.z + v.w;
    float sq  = v.x * v.x + v.y * v.y + v.z * v.z + v.w * v.w;
#pragma unroll
    for (int off = 16; off; off >>= 1) {
        sum += __shfl_xor_sync(0xffffffffu, sum, off);
        sq  += __shfl_xor_sync(0xffffffffu, sq, off);
    }
    int wid = tid >> 5, lane = tid & 31;
    if (lane == 0) { red0[wid] = sum; red1[wid] = sq; }
    __syncthreads();

    float tot = 0.0f, totsq = 0.0f;
#pragma unroll
    for (int w = 0; w < 8; w++) { tot += red0[w]; totsq += red1[w]; }

    float mu = tot * (1.0f / DIM_);
    float var = totsq * (1.0f / DIM_) - mu * mu;
    float rs = rsqrtf(var + 1e-5f);

    int e = tid * 4;
    float4 g  = *(const float4*)(gamma + e);
    float4 be = *(const float4*)(beta + e);
    float4 r = make_float4((v.x - mu) * rs * g.x + be.x,
                           (v.y - mu) * rs * g.y + be.y,
                           (v.z - mu) * rs * g.z + be.z,
                           (v.w - mu) * rs * g.w + be.w);
    *(float4*)(out + (size_t)row * DIM_ + e) = r;
}

// ---------------------------------------------------------------------------
extern "C" void kernel_launch(void* const* d_in, const int* in_sizes, int n_in,
                              void* d_out, int out_size)
{
    const float* x     = (const float*)d_in[0];
    const int*   mask  = (const int*)d_in[1];
    const float* Wq    = (const float*)d_in[2];
    const float* Wk    = (const float*)d_in[3];
    const float* Wv    = (const float*)d_in[4];
    const float* Wo    = (const float*)d_in[5];
    const float* gamma = (const float*)d_in[6];
    const float* beta  = (const float*)d_in[7];
    float* out = (float*)d_out;

    cudaFuncSetAttribute(attn_mma,
                         cudaFuncAttributeMaxDynamicSharedMemorySize, ATTN_SMEM);

    tohalf_kernel<<<dim3(1024, 5), 256>>>(x, Wq, Wk, Wv, Wo);

    qkv_f16<<<dim3(BT / 128, DIM_ / 128, 3), 256>>>();

    attn_mma<<<dim3(TLEN / 128, BSZ * NH), 256, ATTN_SMEM>>>(mask);

    oproj_f16<<<dim3(BT / 128, DIM_ / 128), 256>>>(x);

    ln_kernel<<<BT, 256>>>(gamma, beta, out);
}

// round 14
// speedup vs baseline: 1.3311x; 1.0107x over previous
#include <cuda_runtime.h>
#include <cuda_fp16.h>
#include <math.h>
#include <stddef.h>
#include <stdint.h>

#define BSZ   4
#define TLEN  2048
#define DIM_  1024
#define NH    16
#define HDIM  64
#define BT    (BSZ * TLEN)        // 8192

// Scratch (device-global; no runtime allocation)
__device__ __half g_Xh [(size_t)BT * DIM_];               // x in half
__device__ __half g_Wqh[(size_t)DIM_ * DIM_];
__device__ __half g_Wkh[(size_t)DIM_ * DIM_];
__device__ __half g_Wvh[(size_t)DIM_ * DIM_];
__device__ __half g_Woh[(size_t)DIM_ * DIM_];
__device__ __half g_Qh[(size_t)BSZ * NH * TLEN * HDIM];   // [bh][t][d], rope+scale
__device__ __half g_Kh[(size_t)BSZ * NH * TLEN * HDIM];   // [bh][t][d], rope
__device__ __half g_Vh[(size_t)BSZ * NH * HDIM * TLEN];   // [bh][d][t]
__device__ __half g_Oh[(size_t)BT * DIM_];                // [bt][dim] attention out
__device__ float  g_Hh[(size_t)BT * DIM_];                // residual sum

// ---------------------------------------------------------------------------
// helpers
// ---------------------------------------------------------------------------
__device__ __forceinline__ void mma_f16(float c[4],
                                        const uint32_t a[4],
                                        uint32_t b0, uint32_t b1) {
    asm volatile(
        "mma.sync.aligned.m16n8k16.row.col.f32.f16.f16.f32 "
        "{%0,%1,%2,%3},{%4,%5,%6,%7},{%8,%9},{%0,%1,%2,%3};"
        : "+f"(c[0]), "+f"(c[1]), "+f"(c[2]), "+f"(c[3])
        : "r"(a[0]), "r"(a[1]), "r"(a[2]), "r"(a[3]),
          "r"(b0), "r"(b1));
}

__device__ __forceinline__ void ldsm4(uint32_t& r0, uint32_t& r1,
                                      uint32_t& r2, uint32_t& r3,
                                      uint32_t addr) {
    asm volatile("ldmatrix.sync.aligned.m8n8.x4.shared.b16 {%0,%1,%2,%3}, [%4];"
                 : "=r"(r0), "=r"(r1), "=r"(r2), "=r"(r3) : "r"(addr));
}

__device__ __forceinline__ uint32_t pack_h2(float lo, float hi) {
    __half2 h = __floats2half2_rn(lo, hi);
    return *(uint32_t*)&h;
}

__device__ __forceinline__ void cp16(uint32_t dst_smem, const void* src) {
    asm volatile("cp.async.cg.shared.global [%0], [%1], 16;"
                 :: "r"(dst_smem), "l"(src));
}
#define CP_COMMIT() asm volatile("cp.async.commit_group;" ::: "memory")
#define CP_WAIT(n)  asm volatile("cp.async.wait_group %0;" :: "n"(n) : "memory")

#define SMS 72                         // smem row stride in halves
#define ABUF_H  (128 * SMS)            // halves per A (or B) tile
#define STAGE_H (2 * ABUF_H)           // A + B per stage
#define GEMM_SMEM (2 * STAGE_H * 2)    // 2 stages, bytes = 73728

// ---------------------------------------------------------------------------
// Kernel 0: convert x + 4 weight matrices to half (one-time).
// ---------------------------------------------------------------------------
__global__ __launch_bounds__(256) void tohalf_kernel(
    const float* __restrict__ x,  const float* __restrict__ Wq,
    const float* __restrict__ Wk, const float* __restrict__ Wv,
    const float* __restrict__ Wo)
{
    const float* src; __half* dst; int n4;
    switch (blockIdx.y) {
        case 0: src = x;  dst = g_Xh;  n4 = BT * DIM_ / 4;   break;
        case 1: src = Wq; dst = g_Wqh; n4 = DIM_ * DIM_ / 4; break;
        case 2: src = Wk; dst = g_Wkh; n4 = DIM_ * DIM_ / 4; break;
        case 3: src = Wv; dst = g_Wvh; n4 = DIM_ * DIM_ / 4; break;
        default: src = Wo; dst = g_Woh; n4 = DIM_ * DIM_ / 4; break;
    }
    for (int i = blockIdx.x * 256 + threadIdx.x; i < n4; i += gridDim.x * 256) {
        float4 v = ((const float4*)src)[i];
        *(uint2*)&dst[(size_t)i * 4] =
            make_uint2(pack_h2(v.x, v.y), pack_h2(v.z, v.w));
    }
}

// ---------------------------------------------------------------------------
// GEMM mainloop shared by qkv/oproj: 128x128 CTA, BK=32, double-buffered smem
// (ONE barrier per K-iter), register prefetch for global loads.
// ---------------------------------------------------------------------------
struct GemmCtx {
    const __half* Ah;
    const __half* Bh;
    int m0, n0;
};

__device__ __forceinline__ void gemm_mainloop(
    char* smraw, const GemmCtx& g, int tid, int wm, int wn,
    int lq, int lr, float acc[2][8][4])
{
    __half* sm = (__half*)smraw;
    const int arow = tid >> 2;          // 0..63
    const int ac8  = (tid & 3) * 8;     // 0,8,16,24

    uint4 la[2], lb[2];
#pragma unroll
    for (int r = 0; r < 2; r++) {
        la[r] = *(const uint4*)(g.Ah + (size_t)(g.m0 + arow + 64 * r) * DIM_ + ac8);
        lb[r] = *(const uint4*)(g.Bh + (size_t)(g.n0 + arow + 64 * r) * DIM_ + ac8);
    }
    // store tile 0 into stage 0
#pragma unroll
    for (int r = 0; r < 2; r++) {
        *(uint4*)&sm[(arow + 64 * r) * SMS + ac8]          = la[r];
        *(uint4*)&sm[ABUF_H + (arow + 64 * r) * SMS + ac8] = lb[r];
    }
    __syncthreads();

    for (int it = 0; it < DIM_ / 32; it++) {
        const int cur = it & 1;
        __half* As = sm + cur * STAGE_H;
        __half* Bs = As + ABUF_H;

        const bool more = (it + 1 < DIM_ / 32);
        if (more) {
            int kn = (it + 1) * 32;
#pragma unroll
            for (int r = 0; r < 2; r++) {
                la[r] = *(const uint4*)(g.Ah + (size_t)(g.m0 + arow + 64 * r) * DIM_ + kn + ac8);
                lb[r] = *(const uint4*)(g.Bh + (size_t)(g.n0 + arow + 64 * r) * DIM_ + kn + ac8);
            }
        }

#pragma unroll
        for (int ks = 0; ks < 32; ks += 16) {
            uint32_t a[2][4];
#pragma unroll
            for (int i = 0; i < 2; i++) {
                a[i][0] = *(const uint32_t*)&As[(wm + i * 16 + lq) * SMS + ks + 2 * lr];
                a[i][1] = *(const uint32_t*)&As[(wm + i * 16 + 8 + lq) * SMS + ks + 2 * lr];
                a[i][2] = *(const uint32_t*)&As[(wm + i * 16 + lq) * SMS + ks + 2 * lr + 8];
                a[i][3] = *(const uint32_t*)&As[(wm + i * 16 + 8 + lq) * SMS + ks + 2 * lr + 8];
            }
#pragma unroll
            for (int j = 0; j < 8; j++) {
                uint32_t b0 = *(const uint32_t*)&Bs[(wn + j * 8 + lq) * SMS + ks + 2 * lr];
                uint32_t b1 = *(const uint32_t*)&Bs[(wn + j * 8 + lq) * SMS + ks + 2 * lr + 8];
#pragma unroll
                for (int i = 0; i < 2; i++)
                    mma_f16(acc[i][j], a[i], b0, b1);
            }
        }

        if (more) {
            __half* Ad = sm + (cur ^ 1) * STAGE_H;
#pragma unroll
            for (int r = 0; r < 2; r++) {
                *(uint4*)&Ad[(arow + 64 * r) * SMS + ac8]          = la[r];
                *(uint4*)&Ad[ABUF_H + (arow + 64 * r) * SMS + ac8] = lb[r];
            }
        }
        __syncthreads();
    }
}

// ---------------------------------------------------------------------------
// Kernel 1: QKV projection (RoPE fused in epilogue).
// ---------------------------------------------------------------------------
__global__ __launch_bounds__(256, 2) void qkv_f16()
{
    extern __shared__ char smraw[];
    const int tid  = threadIdx.x;
    const int lane = tid & 31;
    const int wid  = tid >> 5;
    const int lq   = lane >> 2;
    const int lr   = lane & 3;
    const int wm   = (wid & 3) * 32;
    const int wn   = (wid >> 2) * 64;
    const int z    = blockIdx.z;

    GemmCtx g;
    g.Ah = g_Xh;
    g.Bh = (z == 0) ? g_Wqh : (z == 1 ? g_Wkh : g_Wvh);
    g.m0 = blockIdx.x * 128;
    g.n0 = blockIdx.y * 128;

    float acc[2][8][4];
#pragma unroll
    for (int i = 0; i < 2; i++)
#pragma unroll
        for (int j = 0; j < 8; j++)
#pragma unroll
            for (int v = 0; v < 4; v++) acc[i][j][v] = 0.0f;

    gemm_mainloop(smraw, g, tid, wm, wn, lq, lr, acc);

    // ---- Epilogue ----
    if (z < 2) {
        const float C32 = 13.287712379549449f / 32.0f;
        float fr[4][2];
#pragma unroll
        for (int jl = 0; jl < 4; jl++) {
            fr[jl][0] = exp2f(-(float)(jl * 8 + 2 * lr) * C32);
            fr[jl][1] = exp2f(-(float)(jl * 8 + 2 * lr + 1) * C32);
        }
        const float qs = (z == 0) ? 0.125f : 1.0f;
        __half* __restrict__ outp = (z == 0) ? g_Qh : g_Kh;

#pragma unroll
        for (int i = 0; i < 2; i++) {
#pragma unroll
            for (int half_ = 0; half_ < 2; half_++) {
                int row = g.m0 + wm + i * 16 + lq + 8 * half_;
                int bb2 = row >> 11;
                int t   = row & (TLEN - 1);
                float tf = (float)t;
#pragma unroll
                for (int jl = 0; jl < 4; jl++) {
                    int ncol = g.n0 + wn + jl * 8 + 2 * lr;
                    int head = ncol >> 6;
                    int hd1  = ncol & 63;     // < 32
                    float o1[2], o2[2];
#pragma unroll
                    for (int v = 0; v < 2; v++) {
                        float s, c;
                        sincosf(tf * fr[jl][v], &s, &c);
                        float q1 = acc[i][jl][2 * half_ + v];
                        float q2 = acc[i][jl + 4][2 * half_ + v];
                        o1[v] = (q1 * c - q2 * s) * qs;
                        o2[v] = (q2 * c + q1 * s) * qs;
                    }
                    size_t base = (((size_t)(bb2 * NH + head)) * TLEN + t) * HDIM;
                    *(__half2*)&outp[base + hd1] = __floats2half2_rn(o1[0], o1[1]);
                    *(__half2*)&outp[base + hd1 + 32] = __floats2half2_rn(o2[0], o2[1]);
                }
            }
        }
    } else {
#pragma unroll
        for (int i = 0; i < 2; i++) {
#pragma unroll
            for (int half_ = 0; half_ < 2; half_++) {
                int row = g.m0 + wm + i * 16 + lq + 8 * half_;
                int bb2 = row >> 11;
                int t   = row & (TLEN - 1);
#pragma unroll
                for (int j = 0; j < 8; j++) {
                    int ncol = g.n0 + wn + j * 8 + 2 * lr;
                    int head = ncol >> 6;
                    int hd   = ncol & 63;
                    size_t base = ((size_t)(bb2 * NH + head) * HDIM + hd) * TLEN + t;
                    g_Vh[base]        = __float2half(acc[i][j][2 * half_]);
                    g_Vh[base + TLEN] = __float2half(acc[i][j][2 * half_ + 1]);
                }
            }
        }
    }
}

// ---------------------------------------------------------------------------
// Kernel 3: output projection + residual.
// ---------------------------------------------------------------------------
__global__ __launch_bounds__(256, 2) void oproj_f16(const float* __restrict__ x)
{
    extern __shared__ char smraw[];
    const int tid  = threadIdx.x;
    const int lane = tid & 31;
    const int wid  = tid >> 5;
    const int lq   = lane >> 2;
    const int lr   = lane & 3;
    const int wm   = (wid & 3) * 32;
    const int wn   = (wid >> 2) * 64;

    GemmCtx g;
    g.Ah = g_Oh;
    g.Bh = g_Woh;
    g.m0 = blockIdx.x * 128;
    g.n0 = blockIdx.y * 128;

    float acc[2][8][4];
#pragma unroll
    for (int i = 0; i < 2; i++)
#pragma unroll
        for (int j = 0; j < 8; j++)
#pragma unroll
            for (int v = 0; v < 4; v++) acc[i][j][v] = 0.0f;

    gemm_mainloop(smraw, g, tid, wm, wn, lq, lr, acc);

    // Epilogue: h = x + proj -> g_Hh
#pragma unroll
    for (int i = 0; i < 2; i++) {
#pragma unroll
        for (int half_ = 0; half_ < 2; half_++) {
            int row = g.m0 + wm + i * 16 + lq + 8 * half_;
#pragma unroll
            for (int j = 0; j < 8; j++) {
                int ncol = g.n0 + wn + j * 8 + 2 * lr;
                size_t idx = (size_t)row * DIM_ + ncol;
                float2 xr = *(const float2*)(x + idx);
                *(float2*)(g_Hh + idx) =
                    make_float2(acc[i][j][2 * half_] + xr.x,
                                acc[i][j][2 * half_ + 1] + xr.y);
            }
        }
    }
}

// ---------------------------------------------------------------------------
// Kernel 2: flash attention. cp.async double-buffer + ldmatrix fragments.
// ---------------------------------------------------------------------------
#define VH_STRIDE 136
#define KBUF_H  (128 * SMS)
#define VBUF_H  (64 * VH_STRIDE)
#define ATTN_SMEM (2 * KBUF_H * 2 + 2 * VBUF_H * 2 + TLEN * 4)

__global__ __launch_bounds__(256) void attn_mma(const int* __restrict__ mask)
{
    extern __shared__ char smraw[];
    float* madds = (float*)(smraw + 2 * KBUF_H * 2 + 2 * VBUF_H * 2);
    const uint32_t ks_base = (uint32_t)__cvta_generic_to_shared(smraw);
    const uint32_t vh_base = ks_base + 2 * KBUF_H * 2;

    const int tid  = threadIdx.x;
    const int lane = tid & 31;
    const int wid  = tid >> 5;
    const int lq   = lane >> 2;
    const int lr   = lane & 3;
    const int qt   = blockIdx.x;
    const int bh   = blockIdx.y;
    const int bb   = bh >> 4;
    const int q0   = qt * 128 + wid * 16;

    const __half* __restrict__ Qg = g_Qh + ((size_t)bh * TLEN + q0) * HDIM;
    const __half* __restrict__ Kg = g_Kh + (size_t)bh * TLEN * HDIM;
    const __half* __restrict__ Vg = g_Vh + (size_t)bh * HDIM * TLEN;
    const int*    __restrict__ mrow = mask + (size_t)bb * TLEN;

    // ldmatrix B-frag lane address components
    const int br = (lane & 7) + ((lane & 16) ? 8 : 0);
    const int bc = (lane & 8) ? 8 : 0;

#pragma unroll
    for (int i = 0; i < TLEN / 256; i++)
        madds[tid + i * 256] = (1.0f - (float)mrow[tid + i * 256]) * 1e9f;

    uint32_t aq[4][4];
#pragma unroll
    for (int ks = 0; ks < 4; ks++) {
        aq[ks][0] = *(const uint32_t*)&Qg[lq * 64 + ks * 16 + 2 * lr];
        aq[ks][1] = *(const uint32_t*)&Qg[(lq + 8) * 64 + ks * 16 + 2 * lr];
        aq[ks][2] = *(const uint32_t*)&Qg[lq * 64 + ks * 16 + 2 * lr + 8];
        aq[ks][3] = *(const uint32_t*)&Qg[(lq + 8) * 64 + ks * 16 + 2 * lr + 8];
    }

    auto issue_tile = [&](int kt, int buf) {
        uint32_t kdst = ks_base + buf * KBUF_H * 2;
        uint32_t vdst = vh_base + buf * VBUF_H * 2;
#pragma unroll
        for (int i = 0; i < 4; i++) {
            int chunk = tid + i * 256;
            int row = chunk >> 3;
            int c8  = (chunk & 7) * 8;
            cp16(kdst + (row * SMS + c8) * 2,
                 Kg + ((size_t)kt * 128 + row) * 64 + c8);
        }
#pragma unroll
        for (int i = 0; i < 4; i++) {
            int linear = tid + i * 256;
            int d  = linear >> 4;
            int kp = (linear & 15) * 8;
            cp16(vdst + (d * VH_STRIDE + kp) * 2,
                 Vg + (size_t)d * TLEN + kt * 128 + kp);
        }
    };

    float oacc[8][4];
#pragma unroll
    for (int dn = 0; dn < 8; dn++)
#pragma unroll
        for (int v = 0; v < 4; v++) oacc[dn][v] = 0.0f;
    float mA = -1e30f, mB = -1e30f, lA = 0.0f, lB = 0.0f;

    issue_tile(0, 0);
    CP_COMMIT();

    for (int kt = 0; kt < 16; kt++) {
        const int cur = kt & 1;
        if (kt + 1 < 16) {
            issue_tile(kt + 1, cur ^ 1);
            CP_COMMIT();
            CP_WAIT(1);
        } else {
            CP_WAIT(0);
        }
        __syncthreads();

        const uint32_t kb = ks_base + cur * KBUF_H * 2;
        const uint32_t vb = vh_base + cur * VBUF_H * 2;

        // S = Q K^T  (ldmatrix.x4: 16 keys x 16 d per load)
        float sacc[16][4];
#pragma unroll
        for (int j = 0; j < 16; j++)
#pragma unroll
            for (int v = 0; v < 4; v++) sacc[j][v] = 0.0f;

#pragma unroll
        for (int jp = 0; jp < 8; jp++) {
#pragma unroll
            for (int ks = 0; ks < 4; ks++) {
                uint32_t b0, b1, b2, b3;
                ldsm4(b0, b1, b2, b3,
                      kb + ((jp * 16 + br) * SMS + ks * 16 + bc) * 2);
                mma_f16(sacc[2 * jp],     aq[ks], b0, b1);
                mma_f16(sacc[2 * jp + 1], aq[ks], b2, b3);
            }
        }

        // mask + online softmax
        const float* mk = madds + kt * 128;
        float rmaxA = -1e30f, rmaxB = -1e30f;
#pragma unroll
        for (int j = 0; j < 16; j++) {
            float m0v = mk[j * 8 + 2 * lr];
            float m1v = mk[j * 8 + 2 * lr + 1];
            sacc[j][0] -= m0v; sacc[j][1] -= m1v;
            sacc[j][2] -= m0v; sacc[j][3] -= m1v;
            rmaxA = fmaxf(rmaxA, fmaxf(sacc[j][0], sacc[j][1]));
            rmaxB = fmaxf(rmaxB, fmaxf(sacc[j][2], sacc[j][3]));
        }
        rmaxA = fmaxf(rmaxA, __shfl_xor_sync(0xffffffffu, rmaxA, 1));
        rmaxA = fmaxf(rmaxA, __shfl_xor_sync(0xffffffffu, rmaxA, 2));
        rmaxB = fmaxf(rmaxB, __shfl_xor_sync(0xffffffffu, rmaxB, 1));
        rmaxB = fmaxf(rmaxB, __shfl_xor_sync(0xffffffffu, rmaxB, 2));

        float mnA = fmaxf(mA, rmaxA), mnB = fmaxf(mB, rmaxB);
        float cA = __expf(mA - mnA),  cB = __expf(mB - mnB);
        float sumA = 0.0f, sumB = 0.0f;

        uint32_t pa[8][4];
#pragma unroll
        for (int s = 0; s < 8; s++) {
            float p0 = __expf(sacc[2 * s][0] - mnA);
            float p1 = __expf(sacc[2 * s][1] - mnA);
            float p2 = __expf(sacc[2 * s][2] - mnB);
            float p3 = __expf(sacc[2 * s][3] - mnB);
            float p4 = __expf(sacc[2 * s + 1][0] - mnA);
            float p5 = __expf(sacc[2 * s + 1][1] - mnA);
            float p6 = __expf(sacc[2 * s + 1][2] - mnB);
            float p7 = __expf(sacc[2 * s + 1][3] - mnB);
            sumA += p0 + p1 + p4 + p5;
            sumB += p2 + p3 + p6 + p7;
            pa[s][0] = pack_h2(p0, p1);
            pa[s][1] = pack_h2(p2, p3);
            pa[s][2] = pack_h2(p4, p5);
            pa[s][3] = pack_h2(p6, p7);
        }
        sumA += __shfl_xor_sync(0xffffffffu, sumA, 1);
        sumA += __shfl_xor_sync(0xffffffffu, sumA, 2);
        sumB += __shfl_xor_sync(0xffffffffu, sumB, 1);
        sumB += __shfl_xor_sync(0xffffffffu, sumB, 2);

        lA = lA * cA + sumA;  lB = lB * cB + sumB;
        mA = mnA;             mB = mnB;
#pragma unroll
        for (int dn = 0; dn < 8; dn++) {
            oacc[dn][0] *= cA; oacc[dn][1] *= cA;
            oacc[dn][2] *= cB; oacc[dn][3] *= cB;
        }

        // O += P @ V  (ldmatrix.x4: 16 d x 16 keys per load)
#pragma unroll
        for (int s = 0; s < 8; s++) {
#pragma unroll
            for (int dp = 0; dp < 4; dp++) {
                uint32_t b0, b1, b2, b3;
                ldsm4(b0, b1, b2, b3,
                      vb + ((dp * 16 + br) * VH_STRIDE + s * 16 + bc) * 2);
                mma_f16(oacc[2 * dp],     pa[s], b0, b1);
                mma_f16(oacc[2 * dp + 1], pa[s], b2, b3);
            }
        }
        __syncthreads();
    }

    const int head = bh & 15;
    float invA = 1.0f / lA, invB = 1.0f / lB;
    size_t rowA = (size_t)(bb * TLEN + q0 + lq) * DIM_ + head * 64;
    size_t rowB = (size_t)(bb * TLEN + q0 + lq + 8) * DIM_ + head * 64;
#pragma unroll
    for (int dn = 0; dn < 8; dn++) {
        *(__half2*)&g_Oh[rowA + dn * 8 + 2 * lr] =
            __floats2half2_rn(oacc[dn][0] * invA, oacc[dn][1] * invA);
        *(__half2*)&g_Oh[rowB + dn * 8 + 2 * lr] =
            __floats2half2_rn(oacc[dn][2] * invB, oacc[dn][3] * invB);
    }
}

// ---------------------------------------------------------------------------
// Kernel 4: LayerNorm per row of h.
// ---------------------------------------------------------------------------
__global__ __launch_bounds__(256) void ln_kernel(
    const float* __restrict__ gamma,
    const float* __restrict__ beta,
    float* __restrict__ out)
{
    __shared__ float red0[8];
    __shared__ float red1[8];
    const int row = blockIdx.x;
    const int tid = threadIdx.x;
    const float* hr = g_Hh + (size_t)row * DIM_;

    float4 v = *(const float4*)(hr + tid * 4);
    float sum = v.x + v.y + v.z + v.w;
    float sq  = v.x * v.x + v.y * v.y + v.z * v.z + v.w * v.w;
#pragma unroll
    for (int off = 16; off; off >>= 1) {
        sum += __shfl_xor_sync(0xffffffffu, sum, off);
        sq  += __shfl_xor_sync(0xffffffffu, sq, off);
    }
    int wid = tid >> 5, lane = tid & 31;
    if (lane == 0) { red0[wid] = sum; red1[wid] = sq; }
    __syncthreads();

    float tot = 0.0f, totsq = 0.0f;
#pragma unroll
    for (int w = 0; w < 8; w++) { tot += red0[w]; totsq += red1[w]; }

    float mu = tot * (1.0f / DIM_);
    float var = totsq * (1.0f / DIM_) - mu * mu;
    float rs = rsqrtf(var + 1e-5f);

    int e = tid * 4;
    float4 g  = *(const float4*)(gamma + e);
    float4 be = *(const float4*)(beta + e);
    float4 r = make_float4((v.x - mu) * rs * g.x + be.x,
                           (v.y - mu) * rs * g.y + be.y,
                           (v.z - mu) * rs * g.z + be.z,
                           (v.w - mu) * rs * g.w + be.w);
    *(float4*)(out + (size_t)row * DIM_ + e) = r;
}

// ---------------------------------------------------------------------------
extern "C" void kernel_launch(void* const* d_in, const int* in_sizes, int n_in,
                              void* d_out, int out_size)
{
    const float* x     = (const float*)d_in[0];
    const int*   mask  = (const int*)d_in[1];
    const float* Wq    = (const float*)d_in[2];
    const float* Wk    = (const float*)d_in[3];
    const float* Wv    = (const float*)d_in[4];
    const float* Wo    = (const float*)d_in[5];
    const float* gamma = (const float*)d_in[6];
    const float* beta  = (const float*)d_in[7];
    float* out = (float*)d_out;

    cudaFuncSetAttribute(qkv_f16,
                         cudaFuncAttributeMaxDynamicSharedMemorySize, GEMM_SMEM);
    cudaFuncSetAttribute(oproj_f16,
                         cudaFuncAttributeMaxDynamicSharedMemorySize, GEMM_SMEM);
    cudaFuncSetAttribute(attn_mma,
                         cudaFuncAttributeMaxDynamicSharedMemorySize, ATTN_SMEM);

    tohalf_kernel<<<dim3(1024, 5), 256>>>(x, Wq, Wk, Wv, Wo);

    qkv_f16<<<dim3(BT / 128, DIM_ / 128, 3), 256, GEMM_SMEM>>>();

    attn_mma<<<dim3(TLEN / 128, BSZ * NH), 256, ATTN_SMEM>>>(mask);

    oproj_f16<<<dim3(BT / 128, DIM_ / 128), 256, GEMM_SMEM>>>(x);

    ln_kernel<<<BT, 256>>>(gamma, beta, out);
}

// round 17
// speedup vs baseline: 1.3742x; 1.0324x over previous
#include <cuda_runtime.h>
#include <cuda_fp16.h>
#include <math.h>
#include <stddef.h>
#include <stdint.h>

#define BSZ   4
#define TLEN  2048
#define DIM_  1024
#define NH    16
#define HDIM  64
#define BT    (BSZ * TLEN)        // 8192

// Scratch (device-global; no runtime allocation)
__device__ __half g_Xh [(size_t)BT * DIM_];               // x in half
__device__ __half g_Wqh[(size_t)DIM_ * DIM_];
__device__ __half g_Wkh[(size_t)DIM_ * DIM_];
__device__ __half g_Wvh[(size_t)DIM_ * DIM_];
__device__ __half g_Woh[(size_t)DIM_ * DIM_];
__device__ __half g_Qh[(size_t)BSZ * NH * TLEN * HDIM];   // [bh][t][d], rope+scale
__device__ __half g_Kh[(size_t)BSZ * NH * TLEN * HDIM];   // [bh][t][d], rope
__device__ __half g_Vh[(size_t)BSZ * NH * HDIM * TLEN];   // [bh][d][t]
__device__ __half g_Oh[(size_t)BT * DIM_];                // [bt][dim] attention out
__device__ float  g_Hh[(size_t)BT * DIM_];                // residual sum

// ---------------------------------------------------------------------------
// helpers
// ---------------------------------------------------------------------------
__device__ __forceinline__ void mma_f16(float c[4],
                                        const uint32_t a[4],
                                        uint32_t b0, uint32_t b1) {
    asm volatile(
        "mma.sync.aligned.m16n8k16.row.col.f32.f16.f16.f32 "
        "{%0,%1,%2,%3},{%4,%5,%6,%7},{%8,%9},{%0,%1,%2,%3};"
        : "+f"(c[0]), "+f"(c[1]), "+f"(c[2]), "+f"(c[3])
        : "r"(a[0]), "r"(a[1]), "r"(a[2]), "r"(a[3]),
          "r"(b0), "r"(b1));
}

__device__ __forceinline__ void ldsm4(uint32_t& r0, uint32_t& r1,
                                      uint32_t& r2, uint32_t& r3,
                                      uint32_t addr) {
    asm volatile("ldmatrix.sync.aligned.m8n8.x4.shared.b16 {%0,%1,%2,%3}, [%4];"
                 : "=r"(r0), "=r"(r1), "=r"(r2), "=r"(r3) : "r"(addr));
}

__device__ __forceinline__ uint32_t pack_h2(float lo, float hi) {
    __half2 h = __floats2half2_rn(lo, hi);
    return *(uint32_t*)&h;
}

__device__ __forceinline__ void cp16(uint32_t dst_smem, const void* src) {
    asm volatile("cp.async.cg.shared.global [%0], [%1], 16;"
                 :: "r"(dst_smem), "l"(src));
}
#define CP_COMMIT() asm volatile("cp.async.commit_group;" ::: "memory")
#define CP_WAIT(n)  asm volatile("cp.async.wait_group %0;" :: "n"(n) : "memory")

#define SMS 72                         // smem row stride in halves
#define ABUF_H  (128 * SMS)            // halves per A (or B) tile
#define STAGE_H (2 * ABUF_H)           // A + B per stage
#define GEMM_SMEM (2 * STAGE_H * 2)    // 2 stages, bytes = 73728

// ---------------------------------------------------------------------------
// Kernel 0: convert x + 4 weight matrices to half (one-time).
// ---------------------------------------------------------------------------
__global__ __launch_bounds__(256) void tohalf_kernel(
    const float* __restrict__ x,  const float* __restrict__ Wq,
    const float* __restrict__ Wk, const float* __restrict__ Wv,
    const float* __restrict__ Wo)
{
    const float* src; __half* dst; int n4;
    switch (blockIdx.y) {
        case 0: src = x;  dst = g_Xh;  n4 = BT * DIM_ / 4;   break;
        case 1: src = Wq; dst = g_Wqh; n4 = DIM_ * DIM_ / 4; break;
        case 2: src = Wk; dst = g_Wkh; n4 = DIM_ * DIM_ / 4; break;
        case 3: src = Wv; dst = g_Wvh; n4 = DIM_ * DIM_ / 4; break;
        default: src = Wo; dst = g_Woh; n4 = DIM_ * DIM_ / 4; break;
    }
    for (int i = blockIdx.x * 256 + threadIdx.x; i < n4; i += gridDim.x * 256) {
        float4 v = ((const float4*)src)[i];
        *(uint2*)&dst[(size_t)i * 4] =
            make_uint2(pack_h2(v.x, v.y), pack_h2(v.z, v.w));
    }
}

// ---------------------------------------------------------------------------
// GEMM mainloop shared by qkv/oproj (unchanged from R14).
// ---------------------------------------------------------------------------
struct GemmCtx {
    const __half* Ah;
    const __half* Bh;
    int m0, n0;
};

__device__ __forceinline__ void gemm_mainloop(
    char* smraw, const GemmCtx& g, int tid, int wm, int wn,
    int lq, int lr, float acc[2][8][4])
{
    __half* sm = (__half*)smraw;
    const int arow = tid >> 2;          // 0..63
    const int ac8  = (tid & 3) * 8;     // 0,8,16,24

    uint4 la[2], lb[2];
#pragma unroll
    for (int r = 0; r < 2; r++) {
        la[r] = *(const uint4*)(g.Ah + (size_t)(g.m0 + arow + 64 * r) * DIM_ + ac8);
        lb[r] = *(const uint4*)(g.Bh + (size_t)(g.n0 + arow + 64 * r) * DIM_ + ac8);
    }
#pragma unroll
    for (int r = 0; r < 2; r++) {
        *(uint4*)&sm[(arow + 64 * r) * SMS + ac8]          = la[r];
        *(uint4*)&sm[ABUF_H + (arow + 64 * r) * SMS + ac8] = lb[r];
    }
    __syncthreads();

    for (int it = 0; it < DIM_ / 32; it++) {
        const int cur = it & 1;
        __half* As = sm + cur * STAGE_H;
        __half* Bs = As + ABUF_H;

        const bool more = (it + 1 < DIM_ / 32);
        if (more) {
            int kn = (it + 1) * 32;
#pragma unroll
            for (int r = 0; r < 2; r++) {
                la[r] = *(const uint4*)(g.Ah + (size_t)(g.m0 + arow + 64 * r) * DIM_ + kn + ac8);
                lb[r] = *(const uint4*)(g.Bh + (size_t)(g.n0 + arow + 64 * r) * DIM_ + kn + ac8);
            }
        }

#pragma unroll
        for (int ks = 0; ks < 32; ks += 16) {
            uint32_t a[2][4];
#pragma unroll
            for (int i = 0; i < 2; i++) {
                a[i][0] = *(const uint32_t*)&As[(wm + i * 16 + lq) * SMS + ks + 2 * lr];
                a[i][1] = *(const uint32_t*)&As[(wm + i * 16 + 8 + lq) * SMS + ks + 2 * lr];
                a[i][2] = *(const uint32_t*)&As[(wm + i * 16 + lq) * SMS + ks + 2 * lr + 8];
                a[i][3] = *(const uint32_t*)&As[(wm + i * 16 + 8 + lq) * SMS + ks + 2 * lr + 8];
            }
#pragma unroll
            for (int j = 0; j < 8; j++) {
                uint32_t b0 = *(const uint32_t*)&Bs[(wn + j * 8 + lq) * SMS + ks + 2 * lr];
                uint32_t b1 = *(const uint32_t*)&Bs[(wn + j * 8 + lq) * SMS + ks + 2 * lr + 8];
#pragma unroll
                for (int i = 0; i < 2; i++)
                    mma_f16(acc[i][j], a[i], b0, b1);
            }
        }

        if (more) {
            __half* Ad = sm + (cur ^ 1) * STAGE_H;
#pragma unroll
            for (int r = 0; r < 2; r++) {
                *(uint4*)&Ad[(arow + 64 * r) * SMS + ac8]          = la[r];
                *(uint4*)&Ad[ABUF_H + (arow + 64 * r) * SMS + ac8] = lb[r];
            }
        }
        __syncthreads();
    }
}

// ---------------------------------------------------------------------------
// Kernel 1: QKV projection (RoPE fused in epilogue). Unchanged from R14.
// ---------------------------------------------------------------------------
__global__ __launch_bounds__(256, 2) void qkv_f16()
{
    extern __shared__ char smraw[];
    const int tid  = threadIdx.x;
    const int lane = tid & 31;
    const int wid  = tid >> 5;
    const int lq   = lane >> 2;
    const int lr   = lane & 3;
    const int wm   = (wid & 3) * 32;
    const int wn   = (wid >> 2) * 64;
    const int z    = blockIdx.z;

    GemmCtx g;
    g.Ah = g_Xh;
    g.Bh = (z == 0) ? g_Wqh : (z == 1 ? g_Wkh : g_Wvh);
    g.m0 = blockIdx.x * 128;
    g.n0 = blockIdx.y * 128;

    float acc[2][8][4];
#pragma unroll
    for (int i = 0; i < 2; i++)
#pragma unroll
        for (int j = 0; j < 8; j++)
#pragma unroll
            for (int v = 0; v < 4; v++) acc[i][j][v] = 0.0f;

    gemm_mainloop(smraw, g, tid, wm, wn, lq, lr, acc);

    // ---- Epilogue ----
    if (z < 2) {
        const float C32 = 13.287712379549449f / 32.0f;
        float fr[4][2];
#pragma unroll
        for (int jl = 0; jl < 4; jl++) {
            fr[jl][0] = exp2f(-(float)(jl * 8 + 2 * lr) * C32);
            fr[jl][1] = exp2f(-(float)(jl * 8 + 2 * lr + 1) * C32);
        }
        const float qs = (z == 0) ? 0.125f : 1.0f;
        __half* __restrict__ outp = (z == 0) ? g_Qh : g_Kh;

#pragma unroll
        for (int i = 0; i < 2; i++) {
#pragma unroll
            for (int half_ = 0; half_ < 2; half_++) {
                int row = g.m0 + wm + i * 16 + lq + 8 * half_;
                int bb2 = row >> 11;
                int t   = row & (TLEN - 1);
                float tf = (float)t;
#pragma unroll
                for (int jl = 0; jl < 4; jl++) {
                    int ncol = g.n0 + wn + jl * 8 + 2 * lr;
                    int head = ncol >> 6;
                    int hd1  = ncol & 63;     // < 32
                    float o1[2], o2[2];
#pragma unroll
                    for (int v = 0; v < 2; v++) {
                        float s, c;
                        sincosf(tf * fr[jl][v], &s, &c);
                        float q1 = acc[i][jl][2 * half_ + v];
                        float q2 = acc[i][jl + 4][2 * half_ + v];
                        o1[v] = (q1 * c - q2 * s) * qs;
                        o2[v] = (q2 * c + q1 * s) * qs;
                    }
                    size_t base = (((size_t)(bb2 * NH + head)) * TLEN + t) * HDIM;
                    *(__half2*)&outp[base + hd1] = __floats2half2_rn(o1[0], o1[1]);
                    *(__half2*)&outp[base + hd1 + 32] = __floats2half2_rn(o2[0], o2[1]);
                }
            }
        }
    } else {
#pragma unroll
        for (int i = 0; i < 2; i++) {
#pragma unroll
            for (int half_ = 0; half_ < 2; half_++) {
                int row = g.m0 + wm + i * 16 + lq + 8 * half_;
                int bb2 = row >> 11;
                int t   = row & (TLEN - 1);
#pragma unroll
                for (int j = 0; j < 8; j++) {
                    int ncol = g.n0 + wn + j * 8 + 2 * lr;
                    int head = ncol >> 6;
                    int hd   = ncol & 63;
                    size_t base = ((size_t)(bb2 * NH + head) * HDIM + hd) * TLEN + t;
                    g_Vh[base]        = __float2half(acc[i][j][2 * half_]);
                    g_Vh[base + TLEN] = __float2half(acc[i][j][2 * half_ + 1]);
                }
            }
        }
    }
}

// ---------------------------------------------------------------------------
// Kernel 3: output projection + residual. Unchanged from R14.
// ---------------------------------------------------------------------------
__global__ __launch_bounds__(256, 2) void oproj_f16(const float* __restrict__ x)
{
    extern __shared__ char smraw[];
    const int tid  = threadIdx.x;
    const int lane = tid & 31;
    const int wid  = tid >> 5;
    const int lq   = lane >> 2;
    const int lr   = lane & 3;
    const int wm   = (wid & 3) * 32;
    const int wn   = (wid >> 2) * 64;

    GemmCtx g;
    g.Ah = g_Oh;
    g.Bh = g_Woh;
    g.m0 = blockIdx.x * 128;
    g.n0 = blockIdx.y * 128;

    float acc[2][8][4];
#pragma unroll
    for (int i = 0; i < 2; i++)
#pragma unroll
        for (int j = 0; j < 8; j++)
#pragma unroll
            for (int v = 0; v < 4; v++) acc[i][j][v] = 0.0f;

    gemm_mainloop(smraw, g, tid, wm, wn, lq, lr, acc);

    // Epilogue: h = x + proj -> g_Hh
#pragma unroll
    for (int i = 0; i < 2; i++) {
#pragma unroll
        for (int half_ = 0; half_ < 2; half_++) {
            int row = g.m0 + wm + i * 16 + lq + 8 * half_;
#pragma unroll
            for (int j = 0; j < 8; j++) {
                int ncol = g.n0 + wn + j * 8 + 2 * lr;
                size_t idx = (size_t)row * DIM_ + ncol;
                float2 xr = *(const float2*)(x + idx);
                *(float2*)(g_Hh + idx) =
                    make_float2(acc[i][j][2 * half_] + xr.x,
                                acc[i][j][2 * half_ + 1] + xr.y);
            }
        }
    }
}

// ---------------------------------------------------------------------------
// Kernel 2: flash attention.  64-key softmax chunks -> sacc[8][4]/pa[4][4]
// halves register pressure; __launch_bounds__(256,2) -> 2 CTAs/SM.
// ---------------------------------------------------------------------------
#define VH_STRIDE 136
#define KBUF_H  (128 * SMS)
#define VBUF_H  (64 * VH_STRIDE)
#define ATTN_SMEM (2 * KBUF_H * 2 + 2 * VBUF_H * 2 + TLEN * 4)

__global__ __launch_bounds__(256, 2) void attn_mma(const int* __restrict__ mask)
{
    extern __shared__ char smraw[];
    float* madds = (float*)(smraw + 2 * KBUF_H * 2 + 2 * VBUF_H * 2);
    const uint32_t ks_base = (uint32_t)__cvta_generic_to_shared(smraw);
    const uint32_t vh_base = ks_base + 2 * KBUF_H * 2;

    const int tid  = threadIdx.x;
    const int lane = tid & 31;
    const int wid  = tid >> 5;
    const int lq   = lane >> 2;
    const int lr   = lane & 3;
    const int qt   = blockIdx.x;
    const int bh   = blockIdx.y;
    const int bb   = bh >> 4;
    const int q0   = qt * 128 + wid * 16;

    const __half* __restrict__ Qg = g_Qh + ((size_t)bh * TLEN + q0) * HDIM;
    const __half* __restrict__ Kg = g_Kh + (size_t)bh * TLEN * HDIM;
    const __half* __restrict__ Vg = g_Vh + (size_t)bh * HDIM * TLEN;
    const int*    __restrict__ mrow = mask + (size_t)bb * TLEN;

    // ldmatrix B-frag lane address components
    const int br = (lane & 7) + ((lane & 16) ? 8 : 0);
    const int bc = (lane & 8) ? 8 : 0;

#pragma unroll
    for (int i = 0; i < TLEN / 256; i++)
        madds[tid + i * 256] = (1.0f - (float)mrow[tid + i * 256]) * 1e9f;

    uint32_t aq[4][4];
#pragma unroll
    for (int ks = 0; ks < 4; ks++) {
        aq[ks][0] = *(const uint32_t*)&Qg[lq * 64 + ks * 16 + 2 * lr];
        aq[ks][1] = *(const uint32_t*)&Qg[(lq + 8) * 64 + ks * 16 + 2 * lr];
        aq[ks][2] = *(const uint32_t*)&Qg[lq * 64 + ks * 16 + 2 * lr + 8];
        aq[ks][3] = *(const uint32_t*)&Qg[(lq + 8) * 64 + ks * 16 + 2 * lr + 8];
    }

    auto issue_tile = [&](int kt, int buf) {
        uint32_t kdst = ks_base + buf * KBUF_H * 2;
        uint32_t vdst = vh_base + buf * VBUF_H * 2;
#pragma unroll
        for (int i = 0; i < 4; i++) {
            int chunk = tid + i * 256;
            int row = chunk >> 3;
            int c8  = (chunk & 7) * 8;
            cp16(kdst + (row * SMS + c8) * 2,
                 Kg + ((size_t)kt * 128 + row) * 64 + c8);
        }
#pragma unroll
        for (int i = 0; i < 4; i++) {
            int linear = tid + i * 256;
            int d  = linear >> 4;
            int kp = (linear & 15) * 8;
            cp16(vdst + (d * VH_STRIDE + kp) * 2,
                 Vg + (size_t)d * TLEN + kt * 128 + kp);
        }
    };

    float oacc[8][4];
#pragma unroll
    for (int dn = 0; dn < 8; dn++)
#pragma unroll
        for (int v = 0; v < 4; v++) oacc[dn][v] = 0.0f;
    float mA = -1e30f, mB = -1e30f, lA = 0.0f, lB = 0.0f;

    issue_tile(0, 0);
    CP_COMMIT();

    for (int kt = 0; kt < 16; kt++) {
        const int cur = kt & 1;
        if (kt + 1 < 16) {
            issue_tile(kt + 1, cur ^ 1);
            CP_COMMIT();
            CP_WAIT(1);
        } else {
            CP_WAIT(0);
        }
        __syncthreads();

        const uint32_t kb = ks_base + cur * KBUF_H * 2;
        const uint32_t vb = vh_base + cur * VBUF_H * 2;

        // two 64-key chunks per tile
#pragma unroll
        for (int hk = 0; hk < 2; hk++) {
            // S = Q K^T for this chunk
            float sacc[8][4];
#pragma unroll
            for (int j = 0; j < 8; j++)
#pragma unroll
                for (int v = 0; v < 4; v++) sacc[j][v] = 0.0f;

#pragma unroll
            for (int jp = 0; jp < 4; jp++) {
#pragma unroll
                for (int ks = 0; ks < 4; ks++) {
                    uint32_t b0, b1, b2, b3;
                    ldsm4(b0, b1, b2, b3,
                          kb + ((hk * 64 + jp * 16 + br) * SMS + ks * 16 + bc) * 2);
                    mma_f16(sacc[2 * jp],     aq[ks], b0, b1);
                    mma_f16(sacc[2 * jp + 1], aq[ks], b2, b3);
                }
            }

            // mask + online softmax (64-key chunk)
            const float* mk = madds + kt * 128 + hk * 64;
            float rmaxA = -1e30f, rmaxB = -1e30f;
#pragma unroll
            for (int j = 0; j < 8; j++) {
                float m0v = mk[j * 8 + 2 * lr];
                float m1v = mk[j * 8 + 2 * lr + 1];
                sacc[j][0] -= m0v; sacc[j][1] -= m1v;
                sacc[j][2] -= m0v; sacc[j][3] -= m1v;
                rmaxA = fmaxf(rmaxA, fmaxf(sacc[j][0], sacc[j][1]));
                rmaxB = fmaxf(rmaxB, fmaxf(sacc[j][2], sacc[j][3]));
            }
            rmaxA = fmaxf(rmaxA, __shfl_xor_sync(0xffffffffu, rmaxA, 1));
            rmaxA = fmaxf(rmaxA, __shfl_xor_sync(0xffffffffu, rmaxA, 2));
            rmaxB = fmaxf(rmaxB, __shfl_xor_sync(0xffffffffu, rmaxB, 1));
            rmaxB = fmaxf(rmaxB, __shfl_xor_sync(0xffffffffu, rmaxB, 2));

            float mnA = fmaxf(mA, rmaxA), mnB = fmaxf(mB, rmaxB);
            float cA = __expf(mA - mnA),  cB = __expf(mB - mnB);
            float sumA = 0.0f, sumB = 0.0f;

            uint32_t pa[4][4];
#pragma unroll
            for (int s = 0; s < 4; s++) {
                float p0 = __expf(sacc[2 * s][0] - mnA);
                float p1 = __expf(sacc[2 * s][1] - mnA);
                float p2 = __expf(sacc[2 * s][2] - mnB);
                float p3 = __expf(sacc[2 * s][3] - mnB);
                float p4 = __expf(sacc[2 * s + 1][0] - mnA);
                float p5 = __expf(sacc[2 * s + 1][1] - mnA);
                float p6 = __expf(sacc[2 * s + 1][2] - mnB);
                float p7 = __expf(sacc[2 * s + 1][3] - mnB);
                sumA += p0 + p1 + p4 + p5;
                sumB += p2 + p3 + p6 + p7;
                pa[s][0] = pack_h2(p0, p1);
                pa[s][1] = pack_h2(p2, p3);
                pa[s][2] = pack_h2(p4, p5);
                pa[s][3] = pack_h2(p6, p7);
            }
            sumA += __shfl_xor_sync(0xffffffffu, sumA, 1);
            sumA += __shfl_xor_sync(0xffffffffu, sumA, 2);
            sumB += __shfl_xor_sync(0xffffffffu, sumB, 1);
            sumB += __shfl_xor_sync(0xffffffffu, sumB, 2);

            lA = lA * cA + sumA;  lB = lB * cB + sumB;
            mA = mnA;             mB = mnB;
#pragma unroll
            for (int dn = 0; dn < 8; dn++) {
                oacc[dn][0] *= cA; oacc[dn][1] *= cA;
                oacc[dn][2] *= cB; oacc[dn][3] *= cB;
            }

            // O += P @ V (this chunk's 64 keys)
#pragma unroll
            for (int s = 0; s < 4; s++) {
#pragma unroll
                for (int dp = 0; dp < 4; dp++) {
                    uint32_t b0, b1, b2, b3;
                    ldsm4(b0, b1, b2, b3,
                          vb + ((dp * 16 + br) * VH_STRIDE + hk * 64 + s * 16 + bc) * 2);
                    mma_f16(oacc[2 * dp],     pa[s], b0, b1);
                    mma_f16(oacc[2 * dp + 1], pa[s], b2, b3);
                }
            }
        }
        __syncthreads();
    }

    const int head = bh & 15;
    float invA = 1.0f / lA, invB = 1.0f / lB;
    size_t rowA = (size_t)(bb * TLEN + q0 + lq) * DIM_ + head * 64;
    size_t rowB = (size_t)(bb * TLEN + q0 + lq + 8) * DIM_ + head * 64;
#pragma unroll
    for (int dn = 0; dn < 8; dn++) {
        *(__half2*)&g_Oh[rowA + dn * 8 + 2 * lr] =
            __floats2half2_rn(oacc[dn][0] * invA, oacc[dn][1] * invA);
        *(__half2*)&g_Oh[rowB + dn * 8 + 2 * lr] =
            __floats2half2_rn(oacc[dn][2] * invB, oacc[dn][3] * invB);
    }
}

// ---------------------------------------------------------------------------
// Kernel 4: LayerNorm per row of h.
// ---------------------------------------------------------------------------
__global__ __launch_bounds__(256) void ln_kernel(
    const float* __restrict__ gamma,
    const float* __restrict__ beta,
    float* __restrict__ out)
{
    __shared__ float red0[8];
    __shared__ float red1[8];
    const int row = blockIdx.x;
    const int tid = threadIdx.x;
    const float* hr = g_Hh + (size_t)row * DIM_;

    float4 v = *(const float4*)(hr + tid * 4);
    float sum = v.x + v.y + v.z + v.w;
    float sq  = v.x * v.x + v.y * v.y + v.z * v.z + v.w * v.w;
#pragma unroll
    for (int off = 16; off; off >>= 1) {
        sum += __shfl_xor_sync(0xffffffffu, sum, off);
        sq  += __shfl_xor_sync(0xffffffffu, sq, off);
    }
    int wid = tid >> 5, lane = tid & 31;
    if (lane == 0) { red0[wid] = sum; red1[wid] = sq; }
    __syncthreads();

    float tot = 0.0f, totsq = 0.0f;
#pragma unroll
    for (int w = 0; w < 8; w++) { tot += red0[w]; totsq += red1[w]; }

    float mu = tot * (1.0f / DIM_);
    float var = totsq * (1.0f / DIM_) - mu * mu;
    float rs = rsqrtf(var + 1e-5f);

    int e = tid * 4;
    float4 g  = *(const float4*)(gamma + e);
    float4 be = *(const float4*)(beta + e);
    float4 r = make_float4((v.x - mu) * rs * g.x + be.x,
                           (v.y - mu) * rs * g.y + be.y,
                           (v.z - mu) * rs * g.z + be.z,
                           (v.w - mu) * rs * g.w + be.w);
    *(float4*)(out + (size_t)row * DIM_ + e) = r;
}

// ---------------------------------------------------------------------------
extern "C" void kernel_launch(void* const* d_in, const int* in_sizes, int n_in,
                              void* d_out, int out_size)
{
    const float* x     = (const float*)d_in[0];
    const int*   mask  = (const int*)d_in[1];
    const float* Wq    = (const float*)d_in[2];
    const float* Wk    = (const float*)d_in[3];
    const float* Wv    = (const float*)d_in[4];
    const float* Wo    = (const float*)d_in[5];
    const float* gamma = (const float*)d_in[6];
    const float* beta  = (const float*)d_in[7];
    float* out = (float*)d_out;

    cudaFuncSetAttribute(qkv_f16,
                         cudaFuncAttributeMaxDynamicSharedMemorySize, GEMM_SMEM);
    cudaFuncSetAttribute(oproj_f16,
                         cudaFuncAttributeMaxDynamicSharedMemorySize, GEMM_SMEM);
    cudaFuncSetAttribute(attn_mma,
                         cudaFuncAttributeMaxDynamicSharedMemorySize, ATTN_SMEM);

    tohalf_kernel<<<dim3(1024, 5), 256>>>(x, Wq, Wk, Wv, Wo);

    qkv_f16<<<dim3(BT / 128, DIM_ / 128, 3), 256, GEMM_SMEM>>>();

    attn_mma<<<dim3(TLEN / 128, BSZ * NH), 256, ATTN_SMEM>>>(mask);

    oproj_f16<<<dim3(BT / 128, DIM_ / 128), 256, GEMM_SMEM>>>(x);

    ln_kernel<<<BT, 256>>>(gamma, beta, out);
}